// round 1
// baseline (speedup 1.0000x reference)
#include <cuda_runtime.h>

// ---------------- scratch (device globals; no allocation allowed) ----------
__device__ float  g_buf1[800 * 4 * 30 * 30];   // pooled+relu conv1 output (pre-BN)
__device__ float  g_buf2[800 * 8 * 25];        // pooled+relu conv2 output (pre-BN)
__device__ float  g_zR[800 * 6];               // per-sample z0,z1,R00,R01,R10,R11
__device__ double g_bn1[8];                    // sum[4], sumsq[4]
__device__ double g_bn2[16];                   // sum[8], sumsq[8]

__global__ void k_zero() {
    int t = threadIdx.x;
    if (t < 8)  g_bn1[t] = 0.0;
    if (t < 16) g_bn2[t] = 0.0;
}

// ---------------- conv1: 3->4ch, 9x9 stride2, relu+bias, pool2, BN1 stats --
// grid: 800 images * 6 row-tiles (10 output rows each). block: 160 threads.
// smem input: SoA channel planes [3][27 rows][128 cols], plane stride 3464
// (3464 % 32 == 8 to spread bank usage of the transposing store).
// weights repacked [tap][oc] so one broadcast LDS.128 fetches all 4 oc weights.
#define C1_PLANE 3464
__global__ __launch_bounds__(160) void k_conv1(const float* __restrict__ x,
                                               const float* __restrict__ w,
                                               const float* __restrict__ bias) {
    __shared__ float s_in[3 * C1_PLANE];          // 10392 floats; reused for conv out
    __shared__ __align__(16) float s_w[972];
    __shared__ double s_st[8];

    const int tid  = threadIdx.x;
    const int n    = blockIdx.x / 6;
    const int tile = blockIdx.x % 6;
    const int ir0  = 20 * tile;                   // first input row of tile

    // transposing load: gmem HWC -> smem channel planes
    const float* xb = x + (size_t)n * 49152 + (size_t)ir0 * 384;
    for (int i = tid; i < 27 * 384; i += 160) {
        int c = i % 3;
        int rest = i / 3;
        int col = rest & 127;
        int r = rest >> 7;
        s_in[c * C1_PLANE + r * 128 + col] = xb[i];
    }
    for (int j = tid; j < 972; j += 160) {
        int oc = j & 3, tap = j >> 2;             // tap = ic*81 + ky*9 + kx
        s_w[j] = w[oc * 243 + tap];
    }
    if (tid < 8) s_st[tid] = 0.0;
    __syncthreads();

    // compute: thread -> (row = tid/15, q = tid%15), cols {q, q+15, q+30, q+45}
    float acc[4][4];
#pragma unroll
    for (int p = 0; p < 4; ++p) { acc[p][0] = acc[p][1] = acc[p][2] = acc[p][3] = 0.f; }
    const int row = tid / 15;
    const int q   = tid % 15;

    if (tid < 150) {
        for (int ky = 0; ky < 9; ++ky) {
            const float* wk = s_w + ky * 36;
#pragma unroll
            for (int ic = 0; ic < 3; ++ic) {
                const float* ir = s_in + ic * C1_PLANE + (2 * row + ky) * 128 + 2 * q;
#pragma unroll
                for (int kx = 0; kx < 9; ++kx) {
                    float4 wv = *(const float4*)(wk + (ic * 81 + kx) * 4);
#pragma unroll
                    for (int p = 0; p < 4; ++p) {
                        float v = ir[30 * p + kx];
                        acc[p][0] += v * wv.x;
                        acc[p][1] += v * wv.y;
                        acc[p][2] += v * wv.z;
                        acc[p][3] += v * wv.w;
                    }
                }
            }
        }
    }
    __syncthreads();   // all input reads done; reuse s_in as conv output

    // relu(conv+bias) -> smem layout [ch][row 10][col 60]
    const float b0 = bias[0], b1 = bias[1], b2 = bias[2], b3 = bias[3];
    if (tid < 150) {
#pragma unroll
        for (int p = 0; p < 4; ++p) {
            int col = q + 15 * p;
            s_in[0 * 600 + row * 60 + col] = fmaxf(acc[p][0] + b0, 0.f);
            s_in[1 * 600 + row * 60 + col] = fmaxf(acc[p][1] + b1, 0.f);
            s_in[2 * 600 + row * 60 + col] = fmaxf(acc[p][2] + b2, 0.f);
            s_in[3 * 600 + row * 60 + col] = fmaxf(acc[p][3] + b3, 0.f);
        }
    }
    __syncthreads();

    // 2x2 maxpool -> [ch][5][30], write g_buf1, accumulate BN1 stats
    for (int p = tid; p < 600; p += 160) {
        int c = p / 150, rest = p % 150;
        int pr = rest / 30, pc = rest % 30;
        const float* o = s_in + c * 600 + (2 * pr) * 60 + 2 * pc;
        float v = fmaxf(fmaxf(o[0], o[1]), fmaxf(o[60], o[61]));
        g_buf1[(size_t)n * 3600 + c * 900 + (tile * 5 + pr) * 30 + pc] = v;
        atomicAdd(&s_st[c], (double)v);
        atomicAdd(&s_st[4 + c], (double)v * (double)v);
    }
    __syncthreads();
    if (tid < 8) atomicAdd(&g_bn1[tid], s_st[tid]);
}

// ---------------- conv2: BN1 affine + 4->8ch 9x9 s2, relu+bias, pool2, BN2 -
__global__ __launch_bounds__(256) void k_conv2(const float* __restrict__ w,
                                               const float* __restrict__ bias,
                                               const float* __restrict__ bn1g,
                                               const float* __restrict__ bn1b) {
    __shared__ float img[3600];                   // [ic][30][30], BN applied
    __shared__ __align__(16) float ws[2592];      // [tap][oc]
    __shared__ float out2[968];                   // [oc][11][11]
    __shared__ float sc[4], shf[4], sb[8];
    __shared__ double st[16];

    const int tid = threadIdx.x;
    const int n = blockIdx.x;

    if (tid < 4) {
        double mu = g_bn1[tid] / 720000.0;
        double var = g_bn1[4 + tid] / 720000.0 - mu * mu;
        float s = bn1g[tid] * rsqrtf((float)var + 1e-5f);
        sc[tid] = s;
        shf[tid] = bn1b[tid] - (float)mu * s;
    }
    if (tid < 8)  sb[tid] = bias[tid];
    if (tid < 16) st[tid] = 0.0;
    for (int j = tid; j < 2592; j += 256) {
        int oc = j & 7, tap = j >> 3;
        ws[j] = w[oc * 324 + tap];
    }
    __syncthreads();

    for (int i = tid; i < 3600; i += 256) {
        int c = i / 900;
        img[i] = sc[c] * g_buf1[(size_t)n * 3600 + i] + shf[c];
    }
    __syncthreads();

    if (tid < 242) {
        const int p = tid >> 1, half = tid & 1;   // 121 positions x 2 halves of 4 oc
        const int orow = p / 11, ocol = p % 11;
        float acc[4] = {0.f, 0.f, 0.f, 0.f};
        for (int ic = 0; ic < 4; ++ic) {
            const float* base = img + ic * 900 + (2 * orow) * 30 + 2 * ocol;
            const float* wb = ws + (ic * 81) * 8 + half * 4;
#pragma unroll
            for (int ky = 0; ky < 9; ++ky)
#pragma unroll
                for (int kx = 0; kx < 9; ++kx) {
                    float v = base[ky * 30 + kx];
                    float4 wv = *(const float4*)(wb + (ky * 9 + kx) * 8);
                    acc[0] += v * wv.x; acc[1] += v * wv.y;
                    acc[2] += v * wv.z; acc[3] += v * wv.w;
                }
        }
#pragma unroll
        for (int qq = 0; qq < 4; ++qq) {
            int oc = half * 4 + qq;
            out2[oc * 121 + p] = fmaxf(acc[qq] + sb[oc], 0.f);
        }
    }
    __syncthreads();

    if (tid < 200) {
        int oc = tid / 25, r = tid % 25;
        int pr = r / 5, pc = r % 5;
        const float* o = out2 + oc * 121 + (2 * pr) * 11 + 2 * pc;
        float v = fmaxf(fmaxf(o[0], o[1]), fmaxf(o[11], o[12]));
        g_buf2[(size_t)n * 200 + tid] = v;
        atomicAdd(&st[oc], (double)v);
        atomicAdd(&st[8 + oc], (double)v * (double)v);
    }
    __syncthreads();
    if (tid < 16) atomicAdd(&g_bn2[tid], st[tid]);
}

// ---------------- FC stack: BN2 affine + 200->16->32->{z(2), L(3)} ---------
__global__ __launch_bounds__(128) void k_fc(const float* __restrict__ bn2g,
                                            const float* __restrict__ bn2b,
                                            const float* __restrict__ w1,
                                            const float* __restrict__ b1,
                                            const float* __restrict__ w2,
                                            const float* __restrict__ b2,
                                            const float* __restrict__ wz,
                                            const float* __restrict__ bz,
                                            const float* __restrict__ wL,
                                            const float* __restrict__ bL) {
    __shared__ float s_w1[3200], s_w2[512], s_wz[64], s_wL[96];
    __shared__ float s_b1[16], s_b2[32], s_bz[2], s_bL[3];
    __shared__ float sc[8], shf[8];
    const int tid = threadIdx.x;

    if (tid < 8) {
        double mu = g_bn2[tid] / 20000.0;
        double var = g_bn2[8 + tid] / 20000.0 - mu * mu;
        float s = bn2g[tid] * rsqrtf((float)var + 1e-5f);
        sc[tid] = s;
        shf[tid] = bn2b[tid] - (float)mu * s;
    }
    for (int i = tid; i < 3200; i += 128) s_w1[i] = w1[i];
    for (int i = tid; i < 512;  i += 128) s_w2[i] = w2[i];
    if (tid < 64) s_wz[tid] = wz[tid];
    if (tid < 96) s_wL[tid] = wL[tid];
    if (tid < 16) s_b1[tid] = b1[tid];
    if (tid < 32) s_b2[tid] = b2[tid];
    if (tid < 2)  s_bz[tid] = bz[tid];
    if (tid < 3)  s_bL[tid] = bL[tid];
    __syncthreads();

    const int s = blockIdx.x * 128 + tid;
    if (s >= 800) return;

    float a1[16];
#pragma unroll
    for (int o = 0; o < 16; ++o) a1[o] = s_b1[o];
    const float* f = g_buf2 + (size_t)s * 200;
    for (int c = 0; c < 8; ++c) {
        float scc = sc[c], shc = shf[c];
        for (int kk = 0; kk < 25; ++kk) {
            int k = c * 25 + kk;
            float feat = scc * f[k] + shc;
#pragma unroll
            for (int o = 0; o < 16; ++o) a1[o] += feat * s_w1[o * 200 + k];
        }
    }
#pragma unroll
    for (int o = 0; o < 16; ++o) a1[o] = fmaxf(a1[o], 0.f);

    float a2[32];
#pragma unroll
    for (int o = 0; o < 32; ++o) {
        float t = s_b2[o];
#pragma unroll
        for (int k = 0; k < 16; ++k) t += a1[k] * s_w2[o * 16 + k];
        a2[o] = fmaxf(t, 0.f);
    }

    float z0 = s_bz[0], z1 = s_bz[1];
    float L0 = s_bL[0], L1 = s_bL[1], L2 = s_bL[2];
#pragma unroll
    for (int k = 0; k < 32; ++k) {
        z0 += a2[k] * s_wz[k];
        z1 += a2[k] * s_wz[32 + k];
        L0 += a2[k] * s_wL[k];
        L1 += a2[k] * s_wL[32 + k];
        L2 += a2[k] * s_wL[64 + k];
    }
    float* o = g_zR + (size_t)s * 6;
    o[0] = z0; o[1] = z1;
    o[2] = L0 * L0; o[3] = L0 * L1; o[4] = L0 * L1; o[5] = L1 * L1 + L2 * L2;
}

// ---------------- Kalman filter: 8 warps, one sequence each ---------------
__global__ __launch_bounds__(256) void k_kf(float* __restrict__ out,
                                            const float* __restrict__ A,
                                            const float* __restrict__ B,
                                            const float* __restrict__ C,
                                            const float* __restrict__ Q) {
    __shared__ float sA[16], sC[8], BQBT[16];
    struct WS {
        float h[4], hp[4], s[16], sp[16], t1[16];
        float SpCT[8], S[4], Si[4], Kg[8], M[16], al[2];
    };
    __shared__ WS kw[8];

    const int tid = threadIdx.x;
    if (tid < 16) sA[tid] = A[tid];
    if (tid < 8)  sC[tid] = C[tid];
    if (tid == 0) {
        float BQ[8];
        for (int i = 0; i < 4; ++i)
            for (int k = 0; k < 2; ++k) {
                float t = 0.f;
                for (int j = 0; j < 2; ++j) t += B[i * 2 + j] * Q[j * 2 + k];
                BQ[i * 2 + k] = t;
            }
        for (int i = 0; i < 4; ++i)
            for (int l = 0; l < 4; ++l) {
                float t = 0.f;
                for (int k = 0; k < 2; ++k) t += BQ[i * 2 + k] * B[l * 2 + k];
                BQBT[i * 4 + l] = t;
            }
    }
    __syncthreads();

    const int wp = tid >> 5;   // warp = sequence index b
    const int l  = tid & 31;
    WS& w = kw[wp];
    const int b = wp;

    {   // init: h0 = [z0, 0], s0 = diag(R0, I2)
        const float* zr = g_zR + (size_t)(b * 100) * 6;
        if (l < 4) {
            float hv = (l < 2) ? zr[l] : 0.f;
            w.h[l] = hv;
            out[b * 400 + l] = hv;
        }
        if (l < 16) {
            int i = l >> 2, j = l & 3;
            float v = 0.f;
            if (i < 2 && j < 2) v = zr[2 + i * 2 + j];
            else if (i >= 2 && j >= 2 && i == j) v = 1.f;
            w.s[l] = v;
        }
    }
    __syncwarp();

    for (int t = 1; t < 100; ++t) {
        const float* zr = g_zR + (size_t)(b * 100 + t) * 6;
        const int i4 = l >> 2, j4 = l & 3;

        // S1: t1 = A*s ; hp = A*h
        if (l < 16) {
            float v = 0.f;
#pragma unroll
            for (int k = 0; k < 4; ++k) v += sA[i4 * 4 + k] * w.s[k * 4 + j4];
            w.t1[l] = v;
        } else if (l < 20) {
            int i = l - 16;
            float v = 0.f;
#pragma unroll
            for (int k = 0; k < 4; ++k) v += sA[i * 4 + k] * w.h[k];
            w.hp[i] = v;
        }
        __syncwarp();
        // S2: sp = t1*A^T + BQBT ; alpha = z - C*hp
        if (l < 16) {
            float v = BQBT[l];
#pragma unroll
            for (int k = 0; k < 4; ++k) v += w.t1[i4 * 4 + k] * sA[j4 * 4 + k];
            w.sp[l] = v;
        } else if (l < 18) {
            int i = l - 16;
            float v = zr[i];
#pragma unroll
            for (int k = 0; k < 4; ++k) v -= sC[i * 4 + k] * w.hp[k];
            w.al[i] = v;
        }
        __syncwarp();
        // S3: SpCT = sp*C^T
        if (l < 8) {
            int i = l >> 1, j = l & 1;
            float v = 0.f;
#pragma unroll
            for (int k = 0; k < 4; ++k) v += w.sp[i * 4 + k] * sC[j * 4 + k];
            w.SpCT[l] = v;
        }
        __syncwarp();
        // S4: S = C*SpCT + R
        if (l < 4) {
            int i = l >> 1, j = l & 1;
            float v = zr[2 + l];
#pragma unroll
            for (int k = 0; k < 4; ++k) v += sC[i * 4 + k] * w.SpCT[k * 2 + j];
            w.S[l] = v;
        }
        __syncwarp();
        // S5: Si = inv(S)  (2x2)
        if (l < 4) {
            float det = w.S[0] * w.S[3] - w.S[1] * w.S[2];
            float inv = 1.f / det;
            float v = (l == 0) ? w.S[3] : (l == 3) ? w.S[0] : -w.S[l];
            w.Si[l] = v * inv;
        }
        __syncwarp();
        // S6: K = SpCT*Si
        if (l < 8) {
            int i = l >> 1, j = l & 1;
            float v = 0.f;
#pragma unroll
            for (int k = 0; k < 2; ++k) v += w.SpCT[i * 2 + k] * w.Si[k * 2 + j];
            w.Kg[l] = v;
        }
        __syncwarp();
        // S7: M = I - K*C ; h = hp + K*alpha (+ output)
        if (l < 16) {
            float v = (i4 == j4) ? 1.f : 0.f;
#pragma unroll
            for (int k = 0; k < 2; ++k) v -= w.Kg[i4 * 2 + k] * sC[k * 4 + j4];
            w.M[l] = v;
        } else if (l < 20) {
            int i = l - 16;
            float v = w.hp[i];
#pragma unroll
            for (int k = 0; k < 2; ++k) v += w.Kg[i * 2 + k] * w.al[k];
            w.h[i] = v;
            out[(b * 100 + t) * 4 + i] = v;
        }
        __syncwarp();
        // S8: s = M*sp
        if (l < 16) {
            float v = 0.f;
#pragma unroll
            for (int k = 0; k < 4; ++k) v += w.M[i4 * 4 + k] * w.sp[k * 4 + j4];
            w.s[l] = v;
        }
        __syncwarp();
    }
}

// ---------------- launch ---------------------------------------------------
extern "C" void kernel_launch(void* const* d_in, const int* in_sizes, int n_in,
                              void* d_out, int out_size) {
    const float* x    = (const float*)d_in[0];
    const float* c1w  = (const float*)d_in[1];
    const float* c1b  = (const float*)d_in[2];
    const float* bn1g = (const float*)d_in[3];
    const float* bn1b = (const float*)d_in[4];
    const float* c2w  = (const float*)d_in[5];
    const float* c2b  = (const float*)d_in[6];
    const float* bn2g = (const float*)d_in[7];
    const float* bn2b = (const float*)d_in[8];
    const float* f1w  = (const float*)d_in[9];
    const float* f1b  = (const float*)d_in[10];
    const float* f2w  = (const float*)d_in[11];
    const float* f2b  = (const float*)d_in[12];
    const float* fzw  = (const float*)d_in[13];
    const float* fzb  = (const float*)d_in[14];
    const float* fLw  = (const float*)d_in[15];
    const float* fLb  = (const float*)d_in[16];
    const float* A    = (const float*)d_in[17];
    const float* B    = (const float*)d_in[18];
    const float* C    = (const float*)d_in[19];
    const float* Q    = (const float*)d_in[20];
    float* out = (float*)d_out;

    k_zero<<<1, 32>>>();
    k_conv1<<<4800, 160>>>(x, c1w, c1b);
    k_conv2<<<800, 256>>>(c2w, c2b, bn1g, bn1b);
    k_fc<<<7, 128>>>(bn2g, bn2b, f1w, f1b, f2w, f2b, fzw, fzb, fLw, fLb);
    k_kf<<<1, 256>>>(out, A, B, C, Q);
}

// round 2
// speedup vs baseline: 1.8264x; 1.8264x over previous
#include <cuda_runtime.h>

// ---------------- scratch (device globals; no allocation allowed) ----------
__device__ float  g_buf1[800 * 4 * 30 * 30];   // pooled+relu conv1 output (pre-BN)
__device__ float  g_buf2[800 * 8 * 25];        // pooled+relu conv2 output (pre-BN)
__device__ float  g_zR[800 * 6];               // per-sample z0,z1,R00,R01,R10,R11
__device__ double g_bn1[8];                    // sum[4], sumsq[4]
__device__ double g_bn2[16];                   // sum[8], sumsq[8]

__global__ void k_zero() {
    int t = threadIdx.x;
    if (t < 8)  g_bn1[t] = 0.0;
    if (t < 16) g_bn2[t] = 0.0;
}

// ---------------- f32x2 helpers --------------------------------------------
__device__ __forceinline__ unsigned long long pk2(float lo, float hi) {
    unsigned long long r;
    asm("mov.b64 %0, {%1, %2};" : "=l"(r) : "f"(lo), "f"(hi));
    return r;
}
__device__ __forceinline__ void ffma2(unsigned long long& c,
                                      unsigned long long a,
                                      unsigned long long b) {
    asm("fma.rn.f32x2 %0, %1, %2, %0;" : "+l"(c) : "l"(a), "l"(b));
}
__device__ __forceinline__ float2 upk2(unsigned long long v) {
    float2 r;
    asm("mov.b64 {%0, %1}, %2;" : "=f"(r.x), "=f"(r.y) : "l"(v));
    return r;
}

// ---------------- conv1: 3->4ch, 9x9 stride2, bias+relu, pool2, BN1 stats --
// grid: 800 images * 6 tiles (10 conv rows = 5 pooled rows). block: 160 = 5 warps.
// warp wp: conv rows {2wp, 2wp+1} (tile-local) == pooled row wp.
// lane l (<30): conv cols {2l, 2l+1} == pooled col l.
// Inner: packed FFMA2 over oc pairs; inputs register-cached per input row,
// reused across kx and both ky phases (rows r, r+1 share input rows).
#define C1_PS 3464   // 27*128 + 8 pad (fill-store bank spread)
__global__ __launch_bounds__(160) void k_conv1(const float* __restrict__ x,
                                               const float* __restrict__ w,
                                               const float* __restrict__ bias) {
    __shared__ float s_in[3 * C1_PS];                 // 3 channel planes, 27 rows x 128
    __shared__ __align__(16) float s_w[972];          // [tap = ic*81+ky*9+kx][oc0..3]
    __shared__ double s_st[8];

    const int tid  = threadIdx.x;
    const int n    = blockIdx.x / 6;
    const int tile = blockIdx.x % 6;

    // transposing fill: gmem HWC (contiguous) -> smem channel planes
    const float* xb = x + (size_t)n * 49152 + (size_t)(tile * 20) * 384;
    for (int i = tid; i < 10368; i += 160) {          // 27 rows * 384
        int c = i % 3;
        int rest = i / 3;
        int col = rest & 127;
        int r = rest >> 7;
        s_in[c * C1_PS + r * 128 + col] = xb[i];
    }
    for (int j = tid; j < 972; j += 160) {
        int oc = j & 3, tap = j >> 2;                 // tap = ic*81 + ky*9 + kx
        s_w[j] = w[oc * 243 + tap];
    }
    if (tid < 8) s_st[tid] = 0.0;
    __syncthreads();

    const int wp = tid >> 5, l = tid & 31;

    unsigned long long acc[2][2][2];                  // [row][col][ocpair]
#pragma unroll
    for (int r = 0; r < 2; ++r)
#pragma unroll
        for (int c = 0; c < 2; ++c) { acc[r][c][0] = 0ull; acc[r][c][1] = 0ull; }

    if (l < 30) {
#pragma unroll 1
        for (int ic = 0; ic < 3; ++ic) {
            const float* pl = s_in + ic * C1_PS + (4 * wp) * 128 + 4 * l;
            const float* wb = s_w + ic * 324;         // 81 taps * 4 oc
#pragma unroll
            for (int jj = 0; jj < 11; ++jj) {         // input rows for conv rows 2wp,2wp+1
                float4 A0 = *(const float4*)(pl);
                float4 A1 = *(const float4*)(pl + 4);
                float4 A2 = *(const float4*)(pl + 8);
                float v0 = A0.x, v1 = A0.y, v2 = A0.z, v3 = A0.w;
                float v4 = A1.x, v5 = A1.y, v6 = A1.z, v7 = A1.w;
                float v8 = A2.x, v9 = A2.y, v10 = A2.z;
                float vv[11] = {v0, v1, v2, v3, v4, v5, v6, v7, v8, v9, v10};
#pragma unroll
                for (int kx = 0; kx < 9; ++kx) {
                    unsigned long long d0 = pk2(vv[kx], vv[kx]);        // col 2l
                    unsigned long long d1 = pk2(vv[kx + 2], vv[kx + 2]); // col 2l+1
                    if (jj <= 8) {                    // row 0: ky = jj
                        ulonglong2 wv = *(const ulonglong2*)(wb + (jj * 9 + kx) * 4);
                        ffma2(acc[0][0][0], d0, wv.x); ffma2(acc[0][0][1], d0, wv.y);
                        ffma2(acc[0][1][0], d1, wv.x); ffma2(acc[0][1][1], d1, wv.y);
                    }
                    if (jj >= 2) {                    // row 1: ky = jj-2
                        ulonglong2 wv = *(const ulonglong2*)(wb + ((jj - 2) * 9 + kx) * 4);
                        ffma2(acc[1][0][0], d0, wv.x); ffma2(acc[1][0][1], d0, wv.y);
                        ffma2(acc[1][1][0], d1, wv.x); ffma2(acc[1][1][1], d1, wv.y);
                    }
                }
                pl += 128;
            }
        }
    }

    // pool 2x2 in registers: this thread's 4 conv outputs per oc ARE one pool window
    float m[4] = {0.f, 0.f, 0.f, 0.f};
    if (l < 30) {
        float2 p000 = upk2(acc[0][0][0]), p001 = upk2(acc[0][0][1]);
        float2 p010 = upk2(acc[0][1][0]), p011 = upk2(acc[0][1][1]);
        float2 p100 = upk2(acc[1][0][0]), p101 = upk2(acc[1][0][1]);
        float2 p110 = upk2(acc[1][1][0]), p111 = upk2(acc[1][1][1]);
        m[0] = fmaxf(fmaxf(fmaxf(p000.x, p010.x), fmaxf(p100.x, p110.x)) + bias[0], 0.f);
        m[1] = fmaxf(fmaxf(fmaxf(p000.y, p010.y), fmaxf(p100.y, p110.y)) + bias[1], 0.f);
        m[2] = fmaxf(fmaxf(fmaxf(p001.x, p011.x), fmaxf(p101.x, p111.x)) + bias[2], 0.f);
        m[3] = fmaxf(fmaxf(fmaxf(p001.y, p011.y), fmaxf(p101.y, p111.y)) + bias[3], 0.f);
        size_t base = (size_t)n * 3600 + (size_t)(tile * 5 + wp) * 30 + l;
        g_buf1[base]        = m[0];
        g_buf1[base + 900]  = m[1];
        g_buf1[base + 1800] = m[2];
        g_buf1[base + 2700] = m[3];
    }

    // BN1 stats: warp shfl-reduce (doubles), then smem atomics, then 8 global adds
#pragma unroll
    for (int oc = 0; oc < 4; ++oc) {
        double sv = (double)m[oc];
        double sq = sv * sv;
#pragma unroll
        for (int off = 16; off > 0; off >>= 1) {
            sv += __shfl_down_sync(0xffffffffu, sv, off);
            sq += __shfl_down_sync(0xffffffffu, sq, off);
        }
        if (l == 0) {
            atomicAdd(&s_st[oc], sv);
            atomicAdd(&s_st[4 + oc], sq);
        }
    }
    __syncthreads();
    if (tid < 8) atomicAdd(&g_bn1[tid], s_st[tid]);
}

// ---------------- conv2: BN1 affine + 4->8ch 9x9 s2, relu+bias, pool2, BN2 -
__global__ __launch_bounds__(256) void k_conv2(const float* __restrict__ w,
                                               const float* __restrict__ bias,
                                               const float* __restrict__ bn1g,
                                               const float* __restrict__ bn1b) {
    __shared__ float img[3600];                   // [ic][30][30], BN applied
    __shared__ __align__(16) float ws[2592];      // [tap][oc]
    __shared__ float out2[968];                   // [oc][11][11]
    __shared__ float sc[4], shf[4], sb[8];
    __shared__ double st[16];

    const int tid = threadIdx.x;
    const int n = blockIdx.x;

    if (tid < 4) {
        double mu = g_bn1[tid] / 720000.0;
        double var = g_bn1[4 + tid] / 720000.0 - mu * mu;
        float s = bn1g[tid] * rsqrtf((float)var + 1e-5f);
        sc[tid] = s;
        shf[tid] = bn1b[tid] - (float)mu * s;
    }
    if (tid < 8)  sb[tid] = bias[tid];
    if (tid < 16) st[tid] = 0.0;
    for (int j = tid; j < 2592; j += 256) {
        int oc = j & 7, tap = j >> 3;
        ws[j] = w[oc * 324 + tap];
    }
    __syncthreads();

    for (int i = tid; i < 3600; i += 256) {
        int c = i / 900;
        img[i] = sc[c] * g_buf1[(size_t)n * 3600 + i] + shf[c];
    }
    __syncthreads();

    if (tid < 242) {
        const int p = tid >> 1, half = tid & 1;   // 121 positions x 2 halves of 4 oc
        const int orow = p / 11, ocol = p % 11;
        float acc[4] = {0.f, 0.f, 0.f, 0.f};
        for (int ic = 0; ic < 4; ++ic) {
            const float* base = img + ic * 900 + (2 * orow) * 30 + 2 * ocol;
            const float* wb = ws + (ic * 81) * 8 + half * 4;
#pragma unroll
            for (int ky = 0; ky < 9; ++ky)
#pragma unroll
                for (int kx = 0; kx < 9; ++kx) {
                    float v = base[ky * 30 + kx];
                    float4 wv = *(const float4*)(wb + (ky * 9 + kx) * 8);
                    acc[0] += v * wv.x; acc[1] += v * wv.y;
                    acc[2] += v * wv.z; acc[3] += v * wv.w;
                }
        }
#pragma unroll
        for (int qq = 0; qq < 4; ++qq) {
            int oc = half * 4 + qq;
            out2[oc * 121 + p] = fmaxf(acc[qq] + sb[oc], 0.f);
        }
    }
    __syncthreads();

    if (tid < 200) {
        int oc = tid / 25, r = tid % 25;
        int pr = r / 5, pc = r % 5;
        const float* o = out2 + oc * 121 + (2 * pr) * 11 + 2 * pc;
        float v = fmaxf(fmaxf(o[0], o[1]), fmaxf(o[11], o[12]));
        g_buf2[(size_t)n * 200 + tid] = v;
        atomicAdd(&st[oc], (double)v);
        atomicAdd(&st[8 + oc], (double)v * (double)v);
    }
    __syncthreads();
    if (tid < 16) atomicAdd(&g_bn2[tid], st[tid]);
}

// ---------------- FC stack: warp-per-sample, 800 warps ---------------------
// grid 100 x 256 threads (8 warps). fc1 split k over 2 half-warps; fc2 one
// neuron per lane with shfl-broadcast a1; fc3 shfl-tree reductions.
__global__ __launch_bounds__(256) void k_fc(const float* __restrict__ bn2g,
                                            const float* __restrict__ bn2b,
                                            const float* __restrict__ w1,
                                            const float* __restrict__ b1,
                                            const float* __restrict__ w2,
                                            const float* __restrict__ b2,
                                            const float* __restrict__ wz,
                                            const float* __restrict__ bz,
                                            const float* __restrict__ wL,
                                            const float* __restrict__ bL) {
    __shared__ float s_w1[16 * 201];              // padded stride 201: conflict-free
    __shared__ float s_w2t[512];                  // transposed: [k][o]
    __shared__ float s_wz[64], s_wL[96];
    __shared__ float s_b1[16], s_b2[32], s_bz[2], s_bL[3];
    __shared__ float sc[8], shf[8];
    __shared__ float sf[8][200];                  // per-warp BN-applied features
    const int tid = threadIdx.x;

    if (tid < 8) {
        double mu = g_bn2[tid] / 20000.0;
        double var = g_bn2[8 + tid] / 20000.0 - mu * mu;
        float s = bn2g[tid] * rsqrtf((float)var + 1e-5f);
        sc[tid] = s;
        shf[tid] = bn2b[tid] - (float)mu * s;
    }
    for (int i = tid; i < 3200; i += 256) {
        int o = i / 200, k = i % 200;
        s_w1[o * 201 + k] = w1[i];
    }
    for (int i = tid; i < 512; i += 256) {
        int k = i >> 5, o = i & 31;
        s_w2t[i] = w2[o * 16 + k];
    }
    if (tid < 64) s_wz[tid] = wz[tid];
    if (tid < 96) s_wL[tid] = wL[tid];
    if (tid < 16) s_b1[tid] = b1[tid];
    if (tid < 32) s_b2[tid] = b2[tid];
    if (tid < 2)  s_bz[tid] = bz[tid];
    if (tid < 3)  s_bL[tid] = bL[tid];
    __syncthreads();

    const int wp = tid >> 5, l = tid & 31;
    const int s = blockIdx.x * 8 + wp;            // < 800 always

    // stage BN-applied features into per-warp smem
    const float* f = g_buf2 + (size_t)s * 200;
    for (int i = l; i < 200; i += 32) {
        int c = i / 25;
        sf[wp][i] = sc[c] * f[i] + shf[c];
    }
    __syncwarp();

    // fc1: o = l&15, half h = l>>4 covers k in [100h, 100h+100)
    const int o16 = l & 15, h = l >> 4;
    float a = (h == 0) ? s_b1[o16] : 0.f;
    {
        const float* wr = s_w1 + o16 * 201 + h * 100;
        const float* fr = sf[wp] + h * 100;
#pragma unroll 4
        for (int k = 0; k < 100; ++k) a += fr[k] * wr[k];
    }
    a += __shfl_xor_sync(0xffffffffu, a, 16);
    float a1 = fmaxf(a, 0.f);                     // a1[o16] valid in all lanes

    // fc2: lane l -> neuron l
    float t2 = s_b2[l];
#pragma unroll
    for (int k = 0; k < 16; ++k) {
        float ak = __shfl_sync(0xffffffffu, a1, k);
        t2 += ak * s_w2t[k * 32 + l];
    }
    float a2 = fmaxf(t2, 0.f);

    // fc3: 5 dot-products over 32 lanes
    float p0 = a2 * s_wz[l];
    float p1 = a2 * s_wz[32 + l];
    float q0 = a2 * s_wL[l];
    float q1 = a2 * s_wL[32 + l];
    float q2 = a2 * s_wL[64 + l];
#pragma unroll
    for (int off = 16; off > 0; off >>= 1) {
        p0 += __shfl_down_sync(0xffffffffu, p0, off);
        p1 += __shfl_down_sync(0xffffffffu, p1, off);
        q0 += __shfl_down_sync(0xffffffffu, q0, off);
        q1 += __shfl_down_sync(0xffffffffu, q1, off);
        q2 += __shfl_down_sync(0xffffffffu, q2, off);
    }
    if (l == 0) {
        float z0 = p0 + s_bz[0], z1 = p1 + s_bz[1];
        float L0 = q0 + s_bL[0], L1 = q1 + s_bL[1], L2 = q2 + s_bL[2];
        float* o = g_zR + (size_t)s * 6;
        o[0] = z0; o[1] = z1;
        o[2] = L0 * L0; o[3] = L0 * L1; o[4] = L0 * L1; o[5] = L1 * L1 + L2 * L2;
    }
}

// ---------------- Kalman filter: 8 warps, 5 merged stages per step ---------
__global__ __launch_bounds__(256) void k_kf(float* __restrict__ out,
                                            const float* __restrict__ A,
                                            const float* __restrict__ B,
                                            const float* __restrict__ C,
                                            const float* __restrict__ Q) {
    __shared__ float sA[16], sC[8], BQBT[16];
    __shared__ float zsm[4800];                   // all z/R staged in smem
    struct WS {
        float h[4], hp[4], s[16], sp[16], t1[16];
        float SpCT[8], S[4], Kg[8], al[2];
    };
    __shared__ WS kw[8];

    const int tid = threadIdx.x;
    if (tid < 16) sA[tid] = A[tid];
    if (tid < 8)  sC[tid] = C[tid];
    if (tid == 0) {
        float BQ[8];
        for (int i = 0; i < 4; ++i)
            for (int k = 0; k < 2; ++k) {
                float t = 0.f;
                for (int j = 0; j < 2; ++j) t += B[i * 2 + j] * Q[j * 2 + k];
                BQ[i * 2 + k] = t;
            }
        for (int i = 0; i < 4; ++i)
            for (int ll = 0; ll < 4; ++ll) {
                float t = 0.f;
                for (int k = 0; k < 2; ++k) t += BQ[i * 2 + k] * B[ll * 2 + k];
                BQBT[i * 4 + ll] = t;
            }
    }
    for (int i = tid; i < 4800; i += 256) zsm[i] = g_zR[i];
    __syncthreads();

    const int b = tid >> 5;                       // warp = sequence
    const int l = tid & 31;
    WS& w = kw[b];
    const float* zb = zsm + b * 600;

    {   // init: h0 = [z0, 0], s0 = diag(R0, I2)
        if (l < 4) {
            float hv = (l < 2) ? zb[l] : 0.f;
            w.h[l] = hv;
            out[b * 400 + l] = hv;
        }
        if (l < 16) {
            int i = l >> 2, j = l & 3;
            float v = 0.f;
            if (i < 2 && j < 2) v = zb[2 + i * 2 + j];
            else if (i >= 2 && j >= 2 && i == j) v = 1.f;
            w.s[l] = v;
        }
    }
    __syncwarp();

    for (int t = 1; t < 100; ++t) {
        const float* zr = zb + t * 6;
        const int i4 = l >> 2, j4 = l & 3;

        // St1: t1 = A*s ; hp = A*h
        if (l < 16) {
            float v = 0.f;
#pragma unroll
            for (int k = 0; k < 4; ++k) v += sA[i4 * 4 + k] * w.s[k * 4 + j4];
            w.t1[l] = v;
        } else if (l < 20) {
            int i = l - 16;
            float v = 0.f;
#pragma unroll
            for (int k = 0; k < 4; ++k) v += sA[i * 4 + k] * w.h[k];
            w.hp[i] = v;
        }
        __syncwarp();

        // St2: sp = t1*A^T + BQBT ; alpha = z - C*hp
        if (l < 16) {
            float v = BQBT[l];
#pragma unroll
            for (int k = 0; k < 4; ++k) v += w.t1[i4 * 4 + k] * sA[j4 * 4 + k];
            w.sp[l] = v;
        } else if (l < 18) {
            int i = l - 16;
            float v = zr[i];
#pragma unroll
            for (int k = 0; k < 4; ++k) v -= sC[i * 4 + k] * w.hp[k];
            w.al[i] = v;
        }
        __syncwarp();

        // St3: SpCT = sp*C^T (lanes 0-7); S = C*sp*C^T + R (lanes 8-11)
        if (l < 8) {
            int i = l >> 1, j = l & 1;
            float v = 0.f;
#pragma unroll
            for (int k = 0; k < 4; ++k) v += w.sp[i * 4 + k] * sC[j * 4 + k];
            w.SpCT[l] = v;
        } else if (l < 12) {
            int i = (l - 8) >> 1, j = (l - 8) & 1;
            float v = zr[2 + (l - 8)];
#pragma unroll
            for (int k = 0; k < 4; ++k) {
                float row = 0.f;
#pragma unroll
                for (int mm = 0; mm < 4; ++mm) row += w.sp[k * 4 + mm] * sC[j * 4 + mm];
                v += sC[i * 4 + k] * row;
            }
            w.S[(l - 8)] = v;
        }
        __syncwarp();

        // St4: K = SpCT * inv(S)   (2x2 adjugate inverse, per-lane det)
        if (l < 8) {
            int i = l >> 1, j = l & 1;
            float det = w.S[0] * w.S[3] - w.S[1] * w.S[2];
            float inv = 1.f / det;
            float v;
            if (j == 0) v = (w.SpCT[i * 2] * w.S[3] - w.SpCT[i * 2 + 1] * w.S[2]) * inv;
            else        v = (w.SpCT[i * 2 + 1] * w.S[0] - w.SpCT[i * 2] * w.S[1]) * inv;
            w.Kg[l] = v;
        }
        __syncwarp();

        // St5: s = sp - K*(C*sp) ; h = hp + K*alpha (+ output)
        if (l < 16) {
            float c0 = 0.f, c1 = 0.f;
#pragma unroll
            for (int k = 0; k < 4; ++k) {
                c0 += sC[k] * w.sp[k * 4 + j4];
                c1 += sC[4 + k] * w.sp[k * 4 + j4];
            }
            w.s[l] = w.sp[l] - w.Kg[i4 * 2] * c0 - w.Kg[i4 * 2 + 1] * c1;
        } else if (l < 20) {
            int i = l - 16;
            float v = w.hp[i] + w.Kg[i * 2] * w.al[0] + w.Kg[i * 2 + 1] * w.al[1];
            w.h[i] = v;
            out[(b * 100 + t) * 4 + i] = v;
        }
        __syncwarp();
    }
}

// ---------------- launch ---------------------------------------------------
extern "C" void kernel_launch(void* const* d_in, const int* in_sizes, int n_in,
                              void* d_out, int out_size) {
    const float* x    = (const float*)d_in[0];
    const float* c1w  = (const float*)d_in[1];
    const float* c1b  = (const float*)d_in[2];
    const float* bn1g = (const float*)d_in[3];
    const float* bn1b = (const float*)d_in[4];
    const float* c2w  = (const float*)d_in[5];
    const float* c2b  = (const float*)d_in[6];
    const float* bn2g = (const float*)d_in[7];
    const float* bn2b = (const float*)d_in[8];
    const float* f1w  = (const float*)d_in[9];
    const float* f1b  = (const float*)d_in[10];
    const float* f2w  = (const float*)d_in[11];
    const float* f2b  = (const float*)d_in[12];
    const float* fzw  = (const float*)d_in[13];
    const float* fzb  = (const float*)d_in[14];
    const float* fLw  = (const float*)d_in[15];
    const float* fLb  = (const float*)d_in[16];
    const float* A    = (const float*)d_in[17];
    const float* B    = (const float*)d_in[18];
    const float* C    = (const float*)d_in[19];
    const float* Q    = (const float*)d_in[20];
    float* out = (float*)d_out;

    k_zero<<<1, 32>>>();
    k_conv1<<<4800, 160>>>(x, c1w, c1b);
    k_conv2<<<800, 256>>>(c2w, c2b, bn1g, bn1b);
    k_fc<<<100, 256>>>(bn2g, bn2b, f1w, f1b, f2w, f2b, fzw, fzb, fLw, fLb);
    k_kf<<<1, 256>>>(out, A, B, C, Q);
}

// round 4
// speedup vs baseline: 2.2269x; 1.2193x over previous
#include <cuda_runtime.h>

// ---------------- scratch (device globals; no allocation allowed) ----------
__device__ float  g_buf1[800 * 4 * 30 * 30];   // pooled+relu conv1 output (pre-BN)
__device__ float  g_buf2[800 * 8 * 25];        // pooled+relu conv2 output (pre-BN)
__device__ float  g_zR[800 * 6];               // per-sample z0,z1,R00,R01,R10,R11
__device__ double g_bn1[8];                    // sum[4], sumsq[4]
__device__ double g_bn2[16];                   // sum[8], sumsq[8]

__global__ void k_zero() {
    int t = threadIdx.x;
    if (t < 8)  g_bn1[t] = 0.0;
    if (t < 16) g_bn2[t] = 0.0;
}

// ---------------- f32x2 helpers --------------------------------------------
__device__ __forceinline__ unsigned long long pk2(float lo, float hi) {
    unsigned long long r;
    asm("mov.b64 %0, {%1, %2};" : "=l"(r) : "f"(lo), "f"(hi));
    return r;
}
__device__ __forceinline__ void ffma2(unsigned long long& c,
                                      unsigned long long a,
                                      unsigned long long b) {
    asm("fma.rn.f32x2 %0, %1, %2, %0;" : "+l"(c) : "l"(a), "l"(b));
}
__device__ __forceinline__ float2 upk2(unsigned long long v) {
    float2 r;
    asm("mov.b64 {%0, %1}, %2;" : "=f"(r.x), "=f"(r.y) : "l"(v));
    return r;
}

// ---------------- conv1: 3->4ch, 9x9 stride2, bias+relu, pool2, BN1 stats --
// grid: 800 images * 6 tiles (10 conv rows = 5 pooled rows). block: 160 = 5 warps.
// warp wp: conv rows {2wp, 2wp+1}; lane l (<30): conv cols {2l, 2l+1}.
// Packed FFMA2 over oc pairs. Per input row jj we pre-pack dv[i]=(v,v) once
// (11 pk2 serve both row phases and both cols: d1(kx) == d0(kx+2)).
#define C1_PS 3464   // 27*128 + 8 pad
__global__ __launch_bounds__(160, 4) void k_conv1(const float* __restrict__ x,
                                                  const float* __restrict__ w,
                                                  const float* __restrict__ bias) {
    __shared__ float s_in[3 * C1_PS];                 // 3 channel planes, 27 rows x 128
    __shared__ __align__(16) float s_w[972];          // [tap = ic*81+ky*9+kx][oc0..3]
    __shared__ double s_st[8];

    const int tid  = threadIdx.x;
    const int n    = blockIdx.x / 6;
    const int tile = blockIdx.x % 6;

    // transposing fill: gmem HWC (contiguous) -> smem channel planes
    const float* xb = x + (size_t)n * 49152 + (size_t)(tile * 20) * 384;
    for (int i = tid; i < 10368; i += 160) {          // 27 rows * 384
        int c = i % 3;
        int rest = i / 3;
        int col = rest & 127;
        int r = rest >> 7;
        s_in[c * C1_PS + r * 128 + col] = xb[i];
    }
    for (int j = tid; j < 972; j += 160) {
        int oc = j & 3, tap = j >> 2;                 // tap = ic*81 + ky*9 + kx
        s_w[j] = w[oc * 243 + tap];
    }
    if (tid < 8) s_st[tid] = 0.0;
    __syncthreads();

    const int wp = tid >> 5, l = tid & 31;

    unsigned long long acc[2][2][2];                  // [row][col][ocpair]
#pragma unroll
    for (int r = 0; r < 2; ++r)
#pragma unroll
        for (int c = 0; c < 2; ++c) { acc[r][c][0] = 0ull; acc[r][c][1] = 0ull; }

    if (l < 30) {
#pragma unroll 1
        for (int ic = 0; ic < 3; ++ic) {
            const float* pl = s_in + ic * C1_PS + (4 * wp) * 128 + 4 * l;
            const float* wb = s_w + ic * 324;         // 81 taps * 4 oc
#pragma unroll
            for (int jj = 0; jj < 11; ++jj) {         // input rows for conv rows 2wp,2wp+1
                float4 A0 = *(const float4*)(pl);
                float4 A1 = *(const float4*)(pl + 4);
                float4 A2 = *(const float4*)(pl + 8);
                unsigned long long dv[11];
                dv[0] = pk2(A0.x, A0.x); dv[1] = pk2(A0.y, A0.y);
                dv[2] = pk2(A0.z, A0.z); dv[3] = pk2(A0.w, A0.w);
                dv[4] = pk2(A1.x, A1.x); dv[5] = pk2(A1.y, A1.y);
                dv[6] = pk2(A1.z, A1.z); dv[7] = pk2(A1.w, A1.w);
                dv[8] = pk2(A2.x, A2.x); dv[9] = pk2(A2.y, A2.y);
                dv[10] = pk2(A2.z, A2.z);
                if (jj <= 8) {                        // row 0: ky = jj
                    const float* wr = wb + jj * 36;
#pragma unroll
                    for (int kx = 0; kx < 9; ++kx) {
                        ulonglong2 wv = *(const ulonglong2*)(wr + kx * 4);
                        ffma2(acc[0][0][0], dv[kx], wv.x);
                        ffma2(acc[0][0][1], dv[kx], wv.y);
                        ffma2(acc[0][1][0], dv[kx + 2], wv.x);
                        ffma2(acc[0][1][1], dv[kx + 2], wv.y);
                    }
                }
                if (jj >= 2) {                        // row 1: ky = jj-2
                    const float* wr = wb + (jj - 2) * 36;
#pragma unroll
                    for (int kx = 0; kx < 9; ++kx) {
                        ulonglong2 wv = *(const ulonglong2*)(wr + kx * 4);
                        ffma2(acc[1][0][0], dv[kx], wv.x);
                        ffma2(acc[1][0][1], dv[kx], wv.y);
                        ffma2(acc[1][1][0], dv[kx + 2], wv.x);
                        ffma2(acc[1][1][1], dv[kx + 2], wv.y);
                    }
                }
                pl += 128;
            }
        }
    }

    // pool 2x2 in registers: this thread's 4 conv outputs per oc ARE one pool window
    float m[4] = {0.f, 0.f, 0.f, 0.f};
    if (l < 30) {
        float2 p000 = upk2(acc[0][0][0]), p001 = upk2(acc[0][0][1]);
        float2 p010 = upk2(acc[0][1][0]), p011 = upk2(acc[0][1][1]);
        float2 p100 = upk2(acc[1][0][0]), p101 = upk2(acc[1][0][1]);
        float2 p110 = upk2(acc[1][1][0]), p111 = upk2(acc[1][1][1]);
        m[0] = fmaxf(fmaxf(fmaxf(p000.x, p010.x), fmaxf(p100.x, p110.x)) + bias[0], 0.f);
        m[1] = fmaxf(fmaxf(fmaxf(p000.y, p010.y), fmaxf(p100.y, p110.y)) + bias[1], 0.f);
        m[2] = fmaxf(fmaxf(fmaxf(p001.x, p011.x), fmaxf(p101.x, p111.x)) + bias[2], 0.f);
        m[3] = fmaxf(fmaxf(fmaxf(p001.y, p011.y), fmaxf(p101.y, p111.y)) + bias[3], 0.f);
        size_t base = (size_t)n * 3600 + (size_t)(tile * 5 + wp) * 30 + l;
        g_buf1[base]        = m[0];
        g_buf1[base + 900]  = m[1];
        g_buf1[base + 1800] = m[2];
        g_buf1[base + 2700] = m[3];
    }

    // BN1 stats: warp shfl-reduce (doubles), then smem atomics, then 8 global adds
#pragma unroll
    for (int oc = 0; oc < 4; ++oc) {
        double sv = (double)m[oc];
        double sq = sv * sv;
#pragma unroll
        for (int off = 16; off > 0; off >>= 1) {
            sv += __shfl_down_sync(0xffffffffu, sv, off);
            sq += __shfl_down_sync(0xffffffffu, sq, off);
        }
        if (l == 0) {
            atomicAdd(&s_st[oc], sv);
            atomicAdd(&s_st[4 + oc], sq);
        }
    }
    __syncthreads();
    if (tid < 8) atomicAdd(&g_bn1[tid], s_st[tid]);
}

// ---------------- conv2: BN1 affine + 4->8ch 9x9 s2, relu+bias, pool2, BN2 -
__global__ __launch_bounds__(256) void k_conv2(const float* __restrict__ w,
                                               const float* __restrict__ bias,
                                               const float* __restrict__ bn1g,
                                               const float* __restrict__ bn1b) {
    __shared__ float img[3600];                   // [ic][30][30], BN applied
    __shared__ __align__(16) float ws[2592];      // [tap][oc]
    __shared__ float out2[968];                   // [oc][11][11]
    __shared__ float sc[4], shf[4], sb[8];
    __shared__ double st[16];

    const int tid = threadIdx.x;
    const int n = blockIdx.x;

    if (tid < 4) {
        double mu = g_bn1[tid] / 720000.0;
        double var = g_bn1[4 + tid] / 720000.0 - mu * mu;
        float s = bn1g[tid] * rsqrtf((float)var + 1e-5f);
        sc[tid] = s;
        shf[tid] = bn1b[tid] - (float)mu * s;
    }
    if (tid < 8)  sb[tid] = bias[tid];
    if (tid < 16) st[tid] = 0.0;
    for (int j = tid; j < 2592; j += 256) {
        int oc = j & 7, tap = j >> 3;
        ws[j] = w[oc * 324 + tap];
    }
    __syncthreads();

    for (int i = tid; i < 3600; i += 256) {
        int c = i / 900;
        img[i] = sc[c] * g_buf1[(size_t)n * 3600 + i] + shf[c];
    }
    __syncthreads();

    if (tid < 242) {
        const int p = tid >> 1, half = tid & 1;   // 121 positions x 2 halves of 4 oc
        const int orow = p / 11, ocol = p % 11;
        float acc[4] = {0.f, 0.f, 0.f, 0.f};
        for (int ic = 0; ic < 4; ++ic) {
            const float* base = img + ic * 900 + (2 * orow) * 30 + 2 * ocol;
            const float* wb = ws + (ic * 81) * 8 + half * 4;
#pragma unroll
            for (int ky = 0; ky < 9; ++ky)
#pragma unroll
                for (int kx = 0; kx < 9; ++kx) {
                    float v = base[ky * 30 + kx];
                    float4 wv = *(const float4*)(wb + (ky * 9 + kx) * 8);
                    acc[0] += v * wv.x; acc[1] += v * wv.y;
                    acc[2] += v * wv.z; acc[3] += v * wv.w;
                }
        }
#pragma unroll
        for (int qq = 0; qq < 4; ++qq) {
            int oc = half * 4 + qq;
            out2[oc * 121 + p] = fmaxf(acc[qq] + sb[oc], 0.f);
        }
    }
    __syncthreads();

    if (tid < 200) {
        int oc = tid / 25, r = tid % 25;
        int pr = r / 5, pc = r % 5;
        const float* o = out2 + oc * 121 + (2 * pr) * 11 + 2 * pc;
        float v = fmaxf(fmaxf(o[0], o[1]), fmaxf(o[11], o[12]));
        g_buf2[(size_t)n * 200 + tid] = v;
        atomicAdd(&st[oc], (double)v);
        atomicAdd(&st[8 + oc], (double)v * (double)v);
    }
    __syncthreads();
    if (tid < 16) atomicAdd(&g_bn2[tid], st[tid]);
}

// ---------------- FC stack: warp-per-sample, 800 warps ---------------------
__global__ __launch_bounds__(256) void k_fc(const float* __restrict__ bn2g,
                                            const float* __restrict__ bn2b,
                                            const float* __restrict__ w1,
                                            const float* __restrict__ b1,
                                            const float* __restrict__ w2,
                                            const float* __restrict__ b2,
                                            const float* __restrict__ wz,
                                            const float* __restrict__ bz,
                                            const float* __restrict__ wL,
                                            const float* __restrict__ bL) {
    __shared__ __align__(16) float s_w1[16 * 204];  // padded stride 204 (16B aligned rows)
    __shared__ float s_w2t[512];                    // transposed: [k][o]
    __shared__ float s_wz[64], s_wL[96];
    __shared__ float s_b1[16], s_b2[32], s_bz[2], s_bL[3];
    __shared__ float sc[8], shf[8];
    __shared__ __align__(16) float sf[8][200];      // per-warp BN-applied features
    const int tid = threadIdx.x;

    if (tid < 8) {
        double mu = g_bn2[tid] / 20000.0;
        double var = g_bn2[8 + tid] / 20000.0 - mu * mu;
        float s = bn2g[tid] * rsqrtf((float)var + 1e-5f);
        sc[tid] = s;
        shf[tid] = bn2b[tid] - (float)mu * s;
    }
    for (int i = tid; i < 3200; i += 256) {
        int o = i / 200, k = i % 200;
        s_w1[o * 204 + k] = w1[i];
    }
    for (int i = tid; i < 512; i += 256) {
        int k = i >> 5, o = i & 31;
        s_w2t[i] = w2[o * 16 + k];
    }
    if (tid < 64) s_wz[tid] = wz[tid];
    if (tid < 96) s_wL[tid] = wL[tid];
    if (tid < 16) s_b1[tid] = b1[tid];
    if (tid < 32) s_b2[tid] = b2[tid];
    if (tid < 2)  s_bz[tid] = bz[tid];
    if (tid < 3)  s_bL[tid] = bL[tid];
    __syncthreads();

    const int wp = tid >> 5, l = tid & 31;
    const int s = blockIdx.x * 8 + wp;            // < 800 always

    // stage BN-applied features into per-warp smem
    const float* f = g_buf2 + (size_t)s * 200;
    for (int i = l; i < 200; i += 32) {
        int c = i / 25;
        sf[wp][i] = sc[c] * f[i] + shf[c];
    }
    __syncwarp();

    // fc1: o = l&15, half h = l>>4 covers k in [100h, 100h+100); 4-acc float4
    const int o16 = l & 15, h = l >> 4;
    float a;
    {
        const float4* wr = (const float4*)(s_w1 + o16 * 204 + h * 100);
        const float4* fr = (const float4*)(sf[wp] + h * 100);
        float a0 = 0.f, a1_ = 0.f, a2_ = 0.f, a3 = 0.f;
#pragma unroll
        for (int k = 0; k < 25; ++k) {
            float4 wv = wr[k], fv = fr[k];
            a0 += fv.x * wv.x;
            a1_ += fv.y * wv.y;
            a2_ += fv.z * wv.z;
            a3 += fv.w * wv.w;
        }
        a = (a0 + a1_) + (a2_ + a3);
        if (h == 0) a += s_b1[o16];
    }
    a += __shfl_xor_sync(0xffffffffu, a, 16);
    float a1 = fmaxf(a, 0.f);                     // a1[o16] valid in all lanes

    // fc2: lane l -> neuron l
    float t2 = s_b2[l];
#pragma unroll
    for (int k = 0; k < 16; ++k) {
        float ak = __shfl_sync(0xffffffffu, a1, k);
        t2 += ak * s_w2t[k * 32 + l];
    }
    float a2 = fmaxf(t2, 0.f);

    // fc3: 5 dot-products over 32 lanes
    float p0 = a2 * s_wz[l];
    float p1 = a2 * s_wz[32 + l];
    float q0 = a2 * s_wL[l];
    float q1 = a2 * s_wL[32 + l];
    float q2 = a2 * s_wL[64 + l];
#pragma unroll
    for (int off = 16; off > 0; off >>= 1) {
        p0 += __shfl_down_sync(0xffffffffu, p0, off);
        p1 += __shfl_down_sync(0xffffffffu, p1, off);
        q0 += __shfl_down_sync(0xffffffffu, q0, off);
        q1 += __shfl_down_sync(0xffffffffu, q1, off);
        q2 += __shfl_down_sync(0xffffffffu, q2, off);
    }
    if (l == 0) {
        float z0 = p0 + s_bz[0], z1 = p1 + s_bz[1];
        float L0 = q0 + s_bL[0], L1 = q1 + s_bL[1], L2 = q2 + s_bL[2];
        float* o = g_zR + (size_t)s * 6;
        o[0] = z0; o[1] = z1;
        o[2] = L0 * L0; o[3] = L0 * L1; o[4] = L0 * L1; o[5] = L1 * L1 + L2 * L2;
    }
}

// ---------------- Kalman filter: ONE warp, 8 sequences x 4 lanes, all-shfl --
// lane l: group g = l>>2 (sequence), j = l&3 (column index).
// State per lane: sc_[i] = Sigma[i][j] (column j), hj = h[j].
// All lanes execute identical straight-line code; cross-lane via shfl only.
// Single warp launched: no block barrier anywhere.
__global__ __launch_bounds__(32) void k_kf(float* __restrict__ out,
                                           const float* __restrict__ A,
                                           const float* __restrict__ B,
                                           const float* __restrict__ C,
                                           const float* __restrict__ Q) {
    __shared__ float zsm[4800];
    const int l = threadIdx.x;
    for (int i = l; i < 4800; i += 32) zsm[i] = g_zR[i];
    __syncwarp();

    const int g = l >> 2, j = l & 3;
    const int base = l & 28;                      // first lane of the 4-lane group
    const unsigned FULL = 0xffffffffu;

    // replicated constants
    float a_[16], c_[8];
#pragma unroll
    for (int i = 0; i < 16; ++i) a_[i] = A[i];
#pragma unroll
    for (int i = 0; i < 8; ++i) c_[i] = C[i];
    // BQBT column j (per-lane)
    float bq[4];
    {
        float BQ[8];
#pragma unroll
        for (int i = 0; i < 4; ++i)
#pragma unroll
            for (int k = 0; k < 2; ++k) {
                float t = 0.f;
#pragma unroll
                for (int q2 = 0; q2 < 2; ++q2) t += B[i * 2 + q2] * Q[q2 * 2 + k];
                BQ[i * 2 + k] = t;
            }
#pragma unroll
        for (int i = 0; i < 4; ++i) {
            float t = 0.f;
#pragma unroll
            for (int k = 0; k < 2; ++k) t += BQ[i * 2 + k] * B[j * 2 + k];
            bq[i] = t;
        }
    }

    const float* zb = zsm + g * 600;

    // init: h0 = [z0, z1, 0, 0]; Sigma0 col j
    float hj = (j < 2) ? zb[j] : 0.f;
    float sc_[4];
    if (j < 2) { sc_[0] = zb[2 + j]; sc_[1] = zb[4 + j]; sc_[2] = 0.f; sc_[3] = 0.f; }
    else       { sc_[0] = 0.f; sc_[1] = 0.f; sc_[2] = (j == 2) ? 1.f : 0.f; sc_[3] = (j == 3) ? 1.f : 0.f; }
    out[g * 400 + j] = hj;

    for (int t = 1; t < 100; ++t) {
        const float* zr = zb + t * 6;
        float z0 = zr[0], z1 = zr[1];
        float R00 = zr[2], R01 = zr[3], R10 = zr[4], R11 = zr[5];

        // gather h
        float h0 = __shfl_sync(FULL, hj, base);
        float h1 = __shfl_sync(FULL, hj, base + 1);
        float h2 = __shfl_sync(FULL, hj, base + 2);
        float h3 = __shfl_sync(FULL, hj, base + 3);
        // hp_j (local)
        float hp = a_[j * 4] * h0 + a_[j * 4 + 1] * h1 + a_[j * 4 + 2] * h2 + a_[j * 4 + 3] * h3;

        // t1 col j = A * Sigma[:,j]
        float t1[4];
#pragma unroll
        for (int i = 0; i < 4; ++i)
            t1[i] = a_[i * 4] * sc_[0] + a_[i * 4 + 1] * sc_[1] + a_[i * 4 + 2] * sc_[2] + a_[i * 4 + 3] * sc_[3];

        // sp col j = sum_k t1[:,k] * A[j][k] + BQBT[:,j]
        float sp[4] = {bq[0], bq[1], bq[2], bq[3]};
#pragma unroll
        for (int k = 0; k < 4; ++k) {
            float ajk = a_[j * 4 + k];
            float u0 = __shfl_sync(FULL, t1[0], base + k);
            float u1 = __shfl_sync(FULL, t1[1], base + k);
            float u2 = __shfl_sync(FULL, t1[2], base + k);
            float u3 = __shfl_sync(FULL, t1[3], base + k);
            sp[0] += u0 * ajk; sp[1] += u1 * ajk; sp[2] += u2 * ajk; sp[3] += u3 * ajk;
        }

        // alpha (replicated): alpha_i = z_i - sum_k C[i][k] hp_k
        float hp0 = __shfl_sync(FULL, hp, base);
        float hp1 = __shfl_sync(FULL, hp, base + 1);
        float hp2 = __shfl_sync(FULL, hp, base + 2);
        float hp3 = __shfl_sync(FULL, hp, base + 3);
        float al0 = z0 - (c_[0] * hp0 + c_[1] * hp1 + c_[2] * hp2 + c_[3] * hp3);
        float al1 = z1 - (c_[4] * hp0 + c_[5] * hp1 + c_[6] * hp2 + c_[7] * hp3);

        // SpCT[i][j2] = sum_k sp[i][k] C[j2][k]; lane contributes sp[i]*C[j2][j],
        // then butterfly-sum within the 4-lane group (xor 1, xor 2).
        float w0[4], w1[4];
        float c0j = c_[j], c1j = c_[4 + j];
#pragma unroll
        for (int i = 0; i < 4; ++i) { w0[i] = sp[i] * c0j; w1[i] = sp[i] * c1j; }
#pragma unroll
        for (int off = 1; off <= 2; off <<= 1) {
#pragma unroll
            for (int i = 0; i < 4; ++i) {
                w0[i] += __shfl_xor_sync(FULL, w0[i], off);
                w1[i] += __shfl_xor_sync(FULL, w1[i], off);
            }
        }
        // now w0[i] = SpCT[i][0], w1[i] = SpCT[i][1] (replicated in group)

        // S = C * SpCT + R  (replicated 2x2)
        float S00 = c_[0] * w0[0] + c_[1] * w0[1] + c_[2] * w0[2] + c_[3] * w0[3] + R00;
        float S01 = c_[0] * w1[0] + c_[1] * w1[1] + c_[2] * w1[2] + c_[3] * w1[3] + R01;
        float S10 = c_[4] * w0[0] + c_[5] * w0[1] + c_[6] * w0[2] + c_[7] * w0[3] + R10;
        float S11 = c_[4] * w1[0] + c_[5] * w1[1] + c_[6] * w1[2] + c_[7] * w1[3] + R11;
        float inv = 1.0f / (S00 * S11 - S01 * S10);
        float Si00 = S11 * inv, Si01 = -S01 * inv, Si10 = -S10 * inv, Si11 = S00 * inv;

        // K = SpCT * Si (replicated 4x2)
        float K0[4], K1[4];
#pragma unroll
        for (int i = 0; i < 4; ++i) {
            K0[i] = w0[i] * Si00 + w1[i] * Si10;
            K1[i] = w0[i] * Si01 + w1[i] * Si11;
        }

        // h update (local) + output
        hj = hp + K0[j] * al0 + K1[j] * al1;
        out[(g * 100 + t) * 4 + j] = hj;

        // CSp (local, column j): cs_{j2} = sum_k C[j2][k] sp[k]
        float cs0 = c_[0] * sp[0] + c_[1] * sp[1] + c_[2] * sp[2] + c_[3] * sp[3];
        float cs1 = c_[4] * sp[0] + c_[5] * sp[1] + c_[6] * sp[2] + c_[7] * sp[3];
        // Sigma new col j = sp - K[:,0]*cs0 - K[:,1]*cs1
#pragma unroll
        for (int i = 0; i < 4; ++i) sc_[i] = sp[i] - K0[i] * cs0 - K1[i] * cs1;
    }
}

// ---------------- launch ---------------------------------------------------
extern "C" void kernel_launch(void* const* d_in, const int* in_sizes, int n_in,
                              void* d_out, int out_size) {
    const float* x    = (const float*)d_in[0];
    const float* c1w  = (const float*)d_in[1];
    const float* c1b  = (const float*)d_in[2];
    const float* bn1g = (const float*)d_in[3];
    const float* bn1b = (const float*)d_in[4];
    const float* c2w  = (const float*)d_in[5];
    const float* c2b  = (const float*)d_in[6];
    const float* bn2g = (const float*)d_in[7];
    const float* bn2b = (const float*)d_in[8];
    const float* f1w  = (const float*)d_in[9];
    const float* f1b  = (const float*)d_in[10];
    const float* f2w  = (const float*)d_in[11];
    const float* f2b  = (const float*)d_in[12];
    const float* fzw  = (const float*)d_in[13];
    const float* fzb  = (const float*)d_in[14];
    const float* fLw  = (const float*)d_in[15];
    const float* fLb  = (const float*)d_in[16];
    const float* A    = (const float*)d_in[17];
    const float* B    = (const float*)d_in[18];
    const float* C    = (const float*)d_in[19];
    const float* Q    = (const float*)d_in[20];
    float* out = (float*)d_out;

    k_zero<<<1, 32>>>();
    k_conv1<<<4800, 160>>>(x, c1w, c1b);
    k_conv2<<<800, 256>>>(c2w, c2b, bn1g, bn1b);
    k_fc<<<100, 256>>>(bn2g, bn2b, f1w, f1b, f2w, f2b, fzw, fzb, fLw, fLb);
    k_kf<<<1, 32>>>(out, A, B, C, Q);
}

// round 5
// speedup vs baseline: 2.2399x; 1.0059x over previous
#include <cuda_runtime.h>

// ---------------- scratch (device globals; no allocation allowed) ----------
__device__ float  g_buf1[800 * 4 * 30 * 30];   // pooled+relu conv1 output (pre-BN)
__device__ float  g_buf2[800 * 8 * 25];        // pooled+relu conv2 output (pre-BN)
__device__ float  g_zR[800 * 6];               // per-sample z0,z1,R00,R01,R10,R11
__device__ double g_bn1[8];                    // sum[4], sumsq[4]
__device__ double g_bn2[16];                   // sum[8], sumsq[8]

__global__ void k_zero() {
    int t = threadIdx.x;
    if (t < 8)  g_bn1[t] = 0.0;
    if (t < 16) g_bn2[t] = 0.0;
}

// ---------------- f32x2 helpers --------------------------------------------
__device__ __forceinline__ unsigned long long pk2(float v) {
    unsigned long long r;
    asm("mov.b64 %0, {%1, %1};" : "=l"(r) : "f"(v));
    return r;
}
__device__ __forceinline__ void ffma2(unsigned long long& c,
                                      unsigned long long a,
                                      unsigned long long b) {
    asm("fma.rn.f32x2 %0, %1, %2, %0;" : "+l"(c) : "l"(a), "l"(b));
}
__device__ __forceinline__ float2 upk2(unsigned long long v) {
    float2 r;
    asm("mov.b64 {%0, %1}, %2;" : "=f"(r.x), "=f"(r.y) : "l"(v));
    return r;
}

// ---------------- conv1: 3->4ch, 9x9 stride2, bias+relu, pool2, BN1 stats --
// grid: 800 images * 6 tiles (10 conv rows = 5 pooled rows). block: 160 = 5 warps.
// warp wp: conv rows {2wp, 2wp+1}; lane l (<30): conv cols {2l, 2l+1}.
// ky-outer loop: weight row ky loaded ONCE (9 ull2) and used for both conv-row
// phases via a 2-row sliding input window (rows base+ky and base+ky+2).
#define C1_PS 3464   // 27*128 + 8 pad
__global__ __launch_bounds__(160, 4) void k_conv1(const float* __restrict__ x,
                                                  const float* __restrict__ w,
                                                  const float* __restrict__ bias) {
    __shared__ float s_in[3 * C1_PS];                 // 3 channel planes, 27 rows x 128
    __shared__ __align__(16) float s_w[972];          // [tap = ic*81+ky*9+kx][oc0..3]
    __shared__ double s_st[8];

    const int tid  = threadIdx.x;
    const int n    = blockIdx.x / 6;
    const int tile = blockIdx.x % 6;

    // transposing fill: gmem HWC (contiguous) -> smem channel planes
    const float* xb = x + (size_t)n * 49152 + (size_t)(tile * 20) * 384;
    for (int i = tid; i < 10368; i += 160) {          // 27 rows * 384
        int c = i % 3;
        int rest = i / 3;
        int col = rest & 127;
        int r = rest >> 7;
        s_in[c * C1_PS + r * 128 + col] = xb[i];
    }
    for (int j = tid; j < 972; j += 160) {
        int oc = j & 3, tap = j >> 2;                 // tap = ic*81 + ky*9 + kx
        s_w[j] = w[oc * 243 + tap];
    }
    if (tid < 8) s_st[tid] = 0.0;
    __syncthreads();

    const int wp = tid >> 5, l = tid & 31;

    unsigned long long acc[2][2][2];                  // [row][col][ocpair]
#pragma unroll
    for (int r = 0; r < 2; ++r)
#pragma unroll
        for (int c = 0; c < 2; ++c) { acc[r][c][0] = 0ull; acc[r][c][1] = 0ull; }

    if (l < 30) {
        float bA[11], bB[11];
#pragma unroll 1
        for (int ic = 0; ic < 3; ++ic) {
            const float* pl0 = s_in + ic * C1_PS + (4 * wp) * 128 + 4 * l;
            const float* wb = s_w + ic * 324;         // 81 taps * 4 oc

            // row loader: 3 LDS.128 -> 11 floats
            auto loadrow = [&](float* b, int r) {
                const float* p = pl0 + r * 128;
                float4 A0 = *(const float4*)(p);
                float4 A1 = *(const float4*)(p + 4);
                float4 A2 = *(const float4*)(p + 8);
                b[0] = A0.x; b[1] = A0.y; b[2] = A0.z; b[3] = A0.w;
                b[4] = A1.x; b[5] = A1.y; b[6] = A1.z; b[7] = A1.w;
                b[8] = A2.x; b[9] = A2.y; b[10] = A2.z;
            };
            // process one ky: cur = input row base+ky (conv row0), nxt = base+ky+2 (row1)
            auto proc = [&](int ky, const float* cur, const float* nxt) {
                const float* wr = wb + ky * 36;
#pragma unroll
                for (int kx = 0; kx < 9; ++kx) {
                    ulonglong2 wv = *(const ulonglong2*)(wr + kx * 4);
                    unsigned long long d0c = pk2(cur[kx]);
                    unsigned long long d1c = pk2(cur[kx + 2]);
                    unsigned long long d0n = pk2(nxt[kx]);
                    unsigned long long d1n = pk2(nxt[kx + 2]);
                    ffma2(acc[0][0][0], d0c, wv.x); ffma2(acc[0][0][1], d0c, wv.y);
                    ffma2(acc[0][1][0], d1c, wv.x); ffma2(acc[0][1][1], d1c, wv.y);
                    ffma2(acc[1][0][0], d0n, wv.x); ffma2(acc[1][0][1], d0n, wv.y);
                    ffma2(acc[1][1][0], d1n, wv.x); ffma2(acc[1][1][1], d1n, wv.y);
                }
            };

            // even ky chain: rows 0,2,...,10
            loadrow(bA, 0); loadrow(bB, 2);
            proc(0, bA, bB); loadrow(bA, 4);
            proc(2, bB, bA); loadrow(bB, 6);
            proc(4, bA, bB); loadrow(bA, 8);
            proc(6, bB, bA); loadrow(bB, 10);
            proc(8, bA, bB);
            // odd ky chain: rows 1,3,...,9
            loadrow(bA, 1); loadrow(bB, 3);
            proc(1, bA, bB); loadrow(bA, 5);
            proc(3, bB, bA); loadrow(bB, 7);
            proc(5, bA, bB); loadrow(bA, 9);
            proc(7, bB, bA);
        }
    }

    // pool 2x2 in registers: this thread's 4 conv outputs per oc ARE one pool window
    float m[4] = {0.f, 0.f, 0.f, 0.f};
    if (l < 30) {
        float2 p000 = upk2(acc[0][0][0]), p001 = upk2(acc[0][0][1]);
        float2 p010 = upk2(acc[0][1][0]), p011 = upk2(acc[0][1][1]);
        float2 p100 = upk2(acc[1][0][0]), p101 = upk2(acc[1][0][1]);
        float2 p110 = upk2(acc[1][1][0]), p111 = upk2(acc[1][1][1]);
        m[0] = fmaxf(fmaxf(fmaxf(p000.x, p010.x), fmaxf(p100.x, p110.x)) + bias[0], 0.f);
        m[1] = fmaxf(fmaxf(fmaxf(p000.y, p010.y), fmaxf(p100.y, p110.y)) + bias[1], 0.f);
        m[2] = fmaxf(fmaxf(fmaxf(p001.x, p011.x), fmaxf(p101.x, p111.x)) + bias[2], 0.f);
        m[3] = fmaxf(fmaxf(fmaxf(p001.y, p011.y), fmaxf(p101.y, p111.y)) + bias[3], 0.f);
        size_t base = (size_t)n * 3600 + (size_t)(tile * 5 + wp) * 30 + l;
        g_buf1[base]        = m[0];
        g_buf1[base + 900]  = m[1];
        g_buf1[base + 1800] = m[2];
        g_buf1[base + 2700] = m[3];
    }

    // BN1 stats: warp shfl-reduce (doubles), then smem atomics, then 8 global adds
#pragma unroll
    for (int oc = 0; oc < 4; ++oc) {
        double sv = (double)m[oc];
        double sq = sv * sv;
#pragma unroll
        for (int off = 16; off > 0; off >>= 1) {
            sv += __shfl_down_sync(0xffffffffu, sv, off);
            sq += __shfl_down_sync(0xffffffffu, sq, off);
        }
        if (l == 0) {
            atomicAdd(&s_st[oc], sv);
            atomicAdd(&s_st[4 + oc], sq);
        }
    }
    __syncthreads();
    if (tid < 8) atomicAdd(&g_bn1[tid], s_st[tid]);
}

// ---------------- conv2: BN1 affine + 4->8ch 9x9 s2, relu+bias, pool2, BN2 -
__global__ __launch_bounds__(256) void k_conv2(const float* __restrict__ w,
                                               const float* __restrict__ bias,
                                               const float* __restrict__ bn1g,
                                               const float* __restrict__ bn1b) {
    __shared__ float img[3600];                   // [ic][30][30], BN applied
    __shared__ __align__(16) float ws[2592];      // [tap][oc]
    __shared__ float out2[968];                   // [oc][11][11]
    __shared__ float sc[4], shf[4], sb[8];
    __shared__ double st[16];

    const int tid = threadIdx.x;
    const int n = blockIdx.x;

    if (tid < 4) {
        double mu = g_bn1[tid] / 720000.0;
        double var = g_bn1[4 + tid] / 720000.0 - mu * mu;
        float s = bn1g[tid] * rsqrtf((float)var + 1e-5f);
        sc[tid] = s;
        shf[tid] = bn1b[tid] - (float)mu * s;
    }
    if (tid < 8)  sb[tid] = bias[tid];
    if (tid < 16) st[tid] = 0.0;
    for (int j = tid; j < 2592; j += 256) {
        int oc = j & 7, tap = j >> 3;
        ws[j] = w[oc * 324 + tap];
    }
    __syncthreads();

    for (int i = tid; i < 3600; i += 256) {
        int c = i / 900;
        img[i] = sc[c] * g_buf1[(size_t)n * 3600 + i] + shf[c];
    }
    __syncthreads();

    if (tid < 242) {
        const int p = tid >> 1, half = tid & 1;   // 121 positions x 2 halves of 4 oc
        const int orow = p / 11, ocol = p % 11;
        unsigned long long a2c[2] = {0ull, 0ull};     // 4 oc as 2 f32x2 pairs
        for (int ic = 0; ic < 4; ++ic) {
            const float* base = img + ic * 900 + (2 * orow) * 30 + 2 * ocol;
            const float* wb = ws + (ic * 81) * 8 + half * 4;
#pragma unroll
            for (int ky = 0; ky < 9; ++ky)
#pragma unroll
                for (int kx = 0; kx < 9; ++kx) {
                    unsigned long long d = pk2(base[ky * 30 + kx]);
                    ulonglong2 wv = *(const ulonglong2*)(wb + (ky * 9 + kx) * 8);
                    ffma2(a2c[0], d, wv.x);
                    ffma2(a2c[1], d, wv.y);
                }
        }
        float2 r0 = upk2(a2c[0]), r1 = upk2(a2c[1]);
        float accv[4] = {r0.x, r0.y, r1.x, r1.y};
#pragma unroll
        for (int qq = 0; qq < 4; ++qq) {
            int oc = half * 4 + qq;
            out2[oc * 121 + p] = fmaxf(accv[qq] + sb[oc], 0.f);
        }
    }
    __syncthreads();

    if (tid < 200) {
        int oc = tid / 25, r = tid % 25;
        int pr = r / 5, pc = r % 5;
        const float* o = out2 + oc * 121 + (2 * pr) * 11 + 2 * pc;
        float v = fmaxf(fmaxf(o[0], o[1]), fmaxf(o[11], o[12]));
        g_buf2[(size_t)n * 200 + tid] = v;
        atomicAdd(&st[oc], (double)v);
        atomicAdd(&st[8 + oc], (double)v * (double)v);
    }
    __syncthreads();
    if (tid < 16) atomicAdd(&g_bn2[tid], st[tid]);
}

// ---------------- FC stack: warp-per-sample, 800 warps ---------------------
__global__ __launch_bounds__(256) void k_fc(const float* __restrict__ bn2g,
                                            const float* __restrict__ bn2b,
                                            const float* __restrict__ w1,
                                            const float* __restrict__ b1,
                                            const float* __restrict__ w2,
                                            const float* __restrict__ b2,
                                            const float* __restrict__ wz,
                                            const float* __restrict__ bz,
                                            const float* __restrict__ wL,
                                            const float* __restrict__ bL) {
    __shared__ __align__(16) float s_w1[16 * 204];  // padded stride 204 (16B aligned rows)
    __shared__ float s_w2t[512];                    // transposed: [k][o]
    __shared__ float s_wz[64], s_wL[96];
    __shared__ float s_b1[16], s_b2[32], s_bz[2], s_bL[3];
    __shared__ float sc[8], shf[8];
    __shared__ __align__(16) float sf[8][200];      // per-warp BN-applied features
    const int tid = threadIdx.x;
    const int wp = tid >> 5, l = tid & 31;
    const int s = blockIdx.x * 8 + wp;              // < 800 always

    // prefetch raw features FIRST (overlap gmem latency with weight staging)
    float raw[7];
    {
        const float* f = g_buf2 + (size_t)s * 200;
#pragma unroll
        for (int j = 0; j < 7; ++j) {
            int i = l + 32 * j;
            raw[j] = (i < 200) ? f[i] : 0.f;
        }
    }

    if (tid < 8) {
        double mu = g_bn2[tid] / 20000.0;
        double var = g_bn2[8 + tid] / 20000.0 - mu * mu;
        float ss = bn2g[tid] * rsqrtf((float)var + 1e-5f);
        sc[tid] = ss;
        shf[tid] = bn2b[tid] - (float)mu * ss;
    }
    // float4 staging of w1 (rows of 200 = 50 float4s each)
    for (int j = tid; j < 800; j += 256) {
        float4 v = ((const float4*)w1)[j];
        int o = j / 50, k0 = (j % 50) * 4;
        *(float4*)(s_w1 + o * 204 + k0) = v;
    }
    for (int i = tid; i < 512; i += 256) {
        int k = i >> 5, o = i & 31;
        s_w2t[i] = w2[o * 16 + k];
    }
    if (tid < 64) s_wz[tid] = wz[tid];
    if (tid < 96) s_wL[tid] = wL[tid];
    if (tid < 16) s_b1[tid] = b1[tid];
    if (tid < 32) s_b2[tid] = b2[tid];
    if (tid < 2)  s_bz[tid] = bz[tid];
    if (tid < 3)  s_bL[tid] = bL[tid];
    __syncthreads();

    // BN-apply prefetched features into per-warp smem
#pragma unroll
    for (int j = 0; j < 7; ++j) {
        int i = l + 32 * j;
        if (i < 200) {
            int c = i / 25;
            sf[wp][i] = sc[c] * raw[j] + shf[c];
        }
    }
    __syncwarp();

    // fc1: o = l&15, half h = l>>4 covers k in [100h, 100h+100); 4-acc float4
    const int o16 = l & 15, h = l >> 4;
    float a;
    {
        const float4* wr = (const float4*)(s_w1 + o16 * 204 + h * 100);
        const float4* fr = (const float4*)(sf[wp] + h * 100);
        float a0 = 0.f, a1_ = 0.f, a2_ = 0.f, a3 = 0.f;
#pragma unroll
        for (int k = 0; k < 25; ++k) {
            float4 wv = wr[k], fv = fr[k];
            a0 += fv.x * wv.x;
            a1_ += fv.y * wv.y;
            a2_ += fv.z * wv.z;
            a3 += fv.w * wv.w;
        }
        a = (a0 + a1_) + (a2_ + a3);
        if (h == 0) a += s_b1[o16];
    }
    a += __shfl_xor_sync(0xffffffffu, a, 16);
    float a1 = fmaxf(a, 0.f);                     // a1[o16] valid in all lanes

    // fc2: lane l -> neuron l
    float t2 = s_b2[l];
#pragma unroll
    for (int k = 0; k < 16; ++k) {
        float ak = __shfl_sync(0xffffffffu, a1, k);
        t2 += ak * s_w2t[k * 32 + l];
    }
    float a2 = fmaxf(t2, 0.f);

    // fc3: 5 dot-products over 32 lanes
    float p0 = a2 * s_wz[l];
    float p1 = a2 * s_wz[32 + l];
    float q0 = a2 * s_wL[l];
    float q1 = a2 * s_wL[32 + l];
    float q2 = a2 * s_wL[64 + l];
#pragma unroll
    for (int off = 16; off > 0; off >>= 1) {
        p0 += __shfl_down_sync(0xffffffffu, p0, off);
        p1 += __shfl_down_sync(0xffffffffu, p1, off);
        q0 += __shfl_down_sync(0xffffffffu, q0, off);
        q1 += __shfl_down_sync(0xffffffffu, q1, off);
        q2 += __shfl_down_sync(0xffffffffu, q2, off);
    }
    if (l == 0) {
        float z0 = p0 + s_bz[0], z1 = p1 + s_bz[1];
        float L0 = q0 + s_bL[0], L1 = q1 + s_bL[1], L2 = q2 + s_bL[2];
        float* o = g_zR + (size_t)s * 6;
        o[0] = z0; o[1] = z1;
        o[2] = L0 * L0; o[3] = L0 * L1; o[4] = L0 * L1; o[5] = L1 * L1 + L2 * L2;
    }
}

// ---------------- Kalman filter: ONE warp, 8 sequences x 4 lanes, all-shfl --
__global__ __launch_bounds__(32) void k_kf(float* __restrict__ out,
                                           const float* __restrict__ A,
                                           const float* __restrict__ B,
                                           const float* __restrict__ C,
                                           const float* __restrict__ Q) {
    __shared__ float zsm[4800];
    const int l = threadIdx.x;
    for (int i = l; i < 4800; i += 32) zsm[i] = g_zR[i];
    __syncwarp();

    const int g = l >> 2, j = l & 3;
    const int base = l & 28;                      // first lane of the 4-lane group
    const unsigned FULL = 0xffffffffu;

    float a_[16], c_[8];
#pragma unroll
    for (int i = 0; i < 16; ++i) a_[i] = A[i];
#pragma unroll
    for (int i = 0; i < 8; ++i) c_[i] = C[i];
    float bq[4];
    {
        float BQ[8];
#pragma unroll
        for (int i = 0; i < 4; ++i)
#pragma unroll
            for (int k = 0; k < 2; ++k) {
                float t = 0.f;
#pragma unroll
                for (int q2 = 0; q2 < 2; ++q2) t += B[i * 2 + q2] * Q[q2 * 2 + k];
                BQ[i * 2 + k] = t;
            }
#pragma unroll
        for (int i = 0; i < 4; ++i) {
            float t = 0.f;
#pragma unroll
            for (int k = 0; k < 2; ++k) t += BQ[i * 2 + k] * B[j * 2 + k];
            bq[i] = t;
        }
    }

    const float* zb = zsm + g * 600;

    float hj = (j < 2) ? zb[j] : 0.f;
    float sc_[4];
    if (j < 2) { sc_[0] = zb[2 + j]; sc_[1] = zb[4 + j]; sc_[2] = 0.f; sc_[3] = 0.f; }
    else       { sc_[0] = 0.f; sc_[1] = 0.f; sc_[2] = (j == 2) ? 1.f : 0.f; sc_[3] = (j == 3) ? 1.f : 0.f; }
    out[g * 400 + j] = hj;

    for (int t = 1; t < 100; ++t) {
        const float* zr = zb + t * 6;
        float z0 = zr[0], z1 = zr[1];
        float R00 = zr[2], R01 = zr[3], R10 = zr[4], R11 = zr[5];

        float h0 = __shfl_sync(FULL, hj, base);
        float h1 = __shfl_sync(FULL, hj, base + 1);
        float h2 = __shfl_sync(FULL, hj, base + 2);
        float h3 = __shfl_sync(FULL, hj, base + 3);
        float hp = a_[j * 4] * h0 + a_[j * 4 + 1] * h1 + a_[j * 4 + 2] * h2 + a_[j * 4 + 3] * h3;

        float t1[4];
#pragma unroll
        for (int i = 0; i < 4; ++i)
            t1[i] = a_[i * 4] * sc_[0] + a_[i * 4 + 1] * sc_[1] + a_[i * 4 + 2] * sc_[2] + a_[i * 4 + 3] * sc_[3];

        float sp[4] = {bq[0], bq[1], bq[2], bq[3]};
#pragma unroll
        for (int k = 0; k < 4; ++k) {
            float ajk = a_[j * 4 + k];
            float u0 = __shfl_sync(FULL, t1[0], base + k);
            float u1 = __shfl_sync(FULL, t1[1], base + k);
            float u2 = __shfl_sync(FULL, t1[2], base + k);
            float u3 = __shfl_sync(FULL, t1[3], base + k);
            sp[0] += u0 * ajk; sp[1] += u1 * ajk; sp[2] += u2 * ajk; sp[3] += u3 * ajk;
        }

        float hp0 = __shfl_sync(FULL, hp, base);
        float hp1 = __shfl_sync(FULL, hp, base + 1);
        float hp2 = __shfl_sync(FULL, hp, base + 2);
        float hp3 = __shfl_sync(FULL, hp, base + 3);
        float al0 = z0 - (c_[0] * hp0 + c_[1] * hp1 + c_[2] * hp2 + c_[3] * hp3);
        float al1 = z1 - (c_[4] * hp0 + c_[5] * hp1 + c_[6] * hp2 + c_[7] * hp3);

        float w0[4], w1[4];
        float c0j = c_[j], c1j = c_[4 + j];
#pragma unroll
        for (int i = 0; i < 4; ++i) { w0[i] = sp[i] * c0j; w1[i] = sp[i] * c1j; }
#pragma unroll
        for (int off = 1; off <= 2; off <<= 1) {
#pragma unroll
            for (int i = 0; i < 4; ++i) {
                w0[i] += __shfl_xor_sync(FULL, w0[i], off);
                w1[i] += __shfl_xor_sync(FULL, w1[i], off);
            }
        }

        float S00 = c_[0] * w0[0] + c_[1] * w0[1] + c_[2] * w0[2] + c_[3] * w0[3] + R00;
        float S01 = c_[0] * w1[0] + c_[1] * w1[1] + c_[2] * w1[2] + c_[3] * w1[3] + R01;
        float S10 = c_[4] * w0[0] + c_[5] * w0[1] + c_[6] * w0[2] + c_[7] * w0[3] + R10;
        float S11 = c_[4] * w1[0] + c_[5] * w1[1] + c_[6] * w1[2] + c_[7] * w1[3] + R11;
        float inv = 1.0f / (S00 * S11 - S01 * S10);
        float Si00 = S11 * inv, Si01 = -S01 * inv, Si10 = -S10 * inv, Si11 = S00 * inv;

        float K0[4], K1[4];
#pragma unroll
        for (int i = 0; i < 4; ++i) {
            K0[i] = w0[i] * Si00 + w1[i] * Si10;
            K1[i] = w0[i] * Si01 + w1[i] * Si11;
        }

        hj = hp + K0[j] * al0 + K1[j] * al1;
        out[(g * 100 + t) * 4 + j] = hj;

        float cs0 = c_[0] * sp[0] + c_[1] * sp[1] + c_[2] * sp[2] + c_[3] * sp[3];
        float cs1 = c_[4] * sp[0] + c_[5] * sp[1] + c_[6] * sp[2] + c_[7] * sp[3];
#pragma unroll
        for (int i = 0; i < 4; ++i) sc_[i] = sp[i] - K0[i] * cs0 - K1[i] * cs1;
    }
}

// ---------------- launch ---------------------------------------------------
extern "C" void kernel_launch(void* const* d_in, const int* in_sizes, int n_in,
                              void* d_out, int out_size) {
    const float* x    = (const float*)d_in[0];
    const float* c1w  = (const float*)d_in[1];
    const float* c1b  = (const float*)d_in[2];
    const float* bn1g = (const float*)d_in[3];
    const float* bn1b = (const float*)d_in[4];
    const float* c2w  = (const float*)d_in[5];
    const float* c2b  = (const float*)d_in[6];
    const float* bn2g = (const float*)d_in[7];
    const float* bn2b = (const float*)d_in[8];
    const float* f1w  = (const float*)d_in[9];
    const float* f1b  = (const float*)d_in[10];
    const float* f2w  = (const float*)d_in[11];
    const float* f2b  = (const float*)d_in[12];
    const float* fzw  = (const float*)d_in[13];
    const float* fzb  = (const float*)d_in[14];
    const float* fLw  = (const float*)d_in[15];
    const float* fLb  = (const float*)d_in[16];
    const float* A    = (const float*)d_in[17];
    const float* B    = (const float*)d_in[18];
    const float* C    = (const float*)d_in[19];
    const float* Q    = (const float*)d_in[20];
    float* out = (float*)d_out;

    k_zero<<<1, 32>>>();
    k_conv1<<<4800, 160>>>(x, c1w, c1b);
    k_conv2<<<800, 256>>>(c2w, c2b, bn1g, bn1b);
    k_fc<<<100, 256>>>(bn2g, bn2b, f1w, f1b, f2w, f2b, fzw, fzb, fLw, fLb);
    k_kf<<<1, 32>>>(out, A, B, C, Q);
}

// round 6
// speedup vs baseline: 2.3284x; 1.0395x over previous
#include <cuda_runtime.h>

// ---------------- scratch (device globals; zero-initialized at load) -------
__device__ float  g_buf1[800 * 4 * 30 * 30];   // pooled+relu conv1 output (pre-BN)
__device__ float  g_buf2[800 * 8 * 25];        // pooled+relu conv2 output (pre-BN)
__device__ float  g_zR[800 * 6];               // per-sample z0,z1,R00,R01,R10,R11
__device__ double g_bn1[8];                    // sum[4], sumsq[4]
__device__ double g_bn2[16];                   // sum[8], sumsq[8]

// zero stats for the NEXT replay (globals start zeroed for the first run)
__global__ void k_zero() {
    int t = threadIdx.x;
    if (t < 8)  g_bn1[t] = 0.0;
    if (t < 16) g_bn2[t] = 0.0;
}

// ---------------- f32x2 helpers --------------------------------------------
__device__ __forceinline__ unsigned long long pk2(float v) {
    unsigned long long r;
    asm("mov.b64 %0, {%1, %1};" : "=l"(r) : "f"(v));
    return r;
}
__device__ __forceinline__ void ffma2(unsigned long long& c,
                                      unsigned long long a,
                                      unsigned long long b) {
    asm("fma.rn.f32x2 %0, %1, %2, %0;" : "+l"(c) : "l"(a), "l"(b));
}
__device__ __forceinline__ float2 upk2(unsigned long long v) {
    float2 r;
    asm("mov.b64 {%0, %1}, %2;" : "=f"(r.x), "=f"(r.y) : "l"(v));
    return r;
}

// ---------------- conv1: 3->4ch, 9x9 stride2, bias+relu, pool2, BN1 stats --
// grid: 800 images * 6 tiles (10 conv rows = 5 pooled rows). block: 160 = 5 warps.
// warp wp: conv rows {2wp, 2wp+1}; lane l (<30): conv cols {2l, 2l+1}.
// ky-outer: weight row loaded once per (ic,ky), reused for both conv-row phases
// via a 2-row sliding input window.
#define C1_PS 3464   // 27*128 + 8 pad
__global__ __launch_bounds__(160, 4) void k_conv1(const float* __restrict__ x,
                                                  const float* __restrict__ w,
                                                  const float* __restrict__ bias) {
    __shared__ float s_in[3 * C1_PS];                 // 3 channel planes, 27 rows x 128
    __shared__ __align__(16) float s_w[972];          // [tap = ic*81+ky*9+kx][oc0..3]
    __shared__ double s_st[8];

    const int tid  = threadIdx.x;
    const int n    = blockIdx.x / 6;
    const int tile = blockIdx.x % 6;

    // vectorized transposing fill: 17 LDG.128 per thread, scatter STS
    const float4* xb4 = (const float4*)(x + (size_t)n * 49152 + (size_t)(tile * 20) * 384);
    for (int j = tid; j < 2592; j += 160) {           // 2592 float4 = 27 rows * 384
        float4 v = xb4[j];
        int i0 = 4 * j;
        int c = i0 % 3;
        int p = i0 / 3;                               // p == row*128 + col (128-wide planes)
        s_in[c * C1_PS + p] = v.x;
        if (++c == 3) { c = 0; ++p; }
        s_in[c * C1_PS + p] = v.y;
        if (++c == 3) { c = 0; ++p; }
        s_in[c * C1_PS + p] = v.z;
        if (++c == 3) { c = 0; ++p; }
        s_in[c * C1_PS + p] = v.w;
    }
    for (int j = tid; j < 972; j += 160) {
        int oc = j & 3, tap = j >> 2;                 // tap = ic*81 + ky*9 + kx
        s_w[j] = w[oc * 243 + tap];
    }
    if (tid < 8) s_st[tid] = 0.0;
    __syncthreads();

    const int wp = tid >> 5, l = tid & 31;

    unsigned long long acc[2][2][2];                  // [row][col][ocpair]
#pragma unroll
    for (int r = 0; r < 2; ++r)
#pragma unroll
        for (int c = 0; c < 2; ++c) { acc[r][c][0] = 0ull; acc[r][c][1] = 0ull; }

    if (l < 30) {
        float bA[11], bB[11];
#pragma unroll 1
        for (int ic = 0; ic < 3; ++ic) {
            const float* pl0 = s_in + ic * C1_PS + (4 * wp) * 128 + 4 * l;
            const float* wb = s_w + ic * 324;         // 81 taps * 4 oc

            auto loadrow = [&](float* b, int r) {
                const float* p = pl0 + r * 128;
                float4 A0 = *(const float4*)(p);
                float4 A1 = *(const float4*)(p + 4);
                float4 A2 = *(const float4*)(p + 8);
                b[0] = A0.x; b[1] = A0.y; b[2] = A0.z; b[3] = A0.w;
                b[4] = A1.x; b[5] = A1.y; b[6] = A1.z; b[7] = A1.w;
                b[8] = A2.x; b[9] = A2.y; b[10] = A2.z;
            };
            auto proc = [&](int ky, const float* cur, const float* nxt) {
                const float* wr = wb + ky * 36;
#pragma unroll
                for (int kx = 0; kx < 9; ++kx) {
                    ulonglong2 wv = *(const ulonglong2*)(wr + kx * 4);
                    unsigned long long d0c = pk2(cur[kx]);
                    unsigned long long d1c = pk2(cur[kx + 2]);
                    unsigned long long d0n = pk2(nxt[kx]);
                    unsigned long long d1n = pk2(nxt[kx + 2]);
                    ffma2(acc[0][0][0], d0c, wv.x); ffma2(acc[0][0][1], d0c, wv.y);
                    ffma2(acc[0][1][0], d1c, wv.x); ffma2(acc[0][1][1], d1c, wv.y);
                    ffma2(acc[1][0][0], d0n, wv.x); ffma2(acc[1][0][1], d0n, wv.y);
                    ffma2(acc[1][1][0], d1n, wv.x); ffma2(acc[1][1][1], d1n, wv.y);
                }
            };

            // even ky chain: rows 0,2,...,10
            loadrow(bA, 0); loadrow(bB, 2);
            proc(0, bA, bB); loadrow(bA, 4);
            proc(2, bB, bA); loadrow(bB, 6);
            proc(4, bA, bB); loadrow(bA, 8);
            proc(6, bB, bA); loadrow(bB, 10);
            proc(8, bA, bB);
            // odd ky chain: rows 1,3,...,9
            loadrow(bA, 1); loadrow(bB, 3);
            proc(1, bA, bB); loadrow(bA, 5);
            proc(3, bB, bA); loadrow(bB, 7);
            proc(5, bA, bB); loadrow(bA, 9);
            proc(7, bB, bA);
        }
    }

    // pool 2x2 in registers
    float m[4] = {0.f, 0.f, 0.f, 0.f};
    if (l < 30) {
        float2 p000 = upk2(acc[0][0][0]), p001 = upk2(acc[0][0][1]);
        float2 p010 = upk2(acc[0][1][0]), p011 = upk2(acc[0][1][1]);
        float2 p100 = upk2(acc[1][0][0]), p101 = upk2(acc[1][0][1]);
        float2 p110 = upk2(acc[1][1][0]), p111 = upk2(acc[1][1][1]);
        m[0] = fmaxf(fmaxf(fmaxf(p000.x, p010.x), fmaxf(p100.x, p110.x)) + bias[0], 0.f);
        m[1] = fmaxf(fmaxf(fmaxf(p000.y, p010.y), fmaxf(p100.y, p110.y)) + bias[1], 0.f);
        m[2] = fmaxf(fmaxf(fmaxf(p001.x, p011.x), fmaxf(p101.x, p111.x)) + bias[2], 0.f);
        m[3] = fmaxf(fmaxf(fmaxf(p001.y, p011.y), fmaxf(p101.y, p111.y)) + bias[3], 0.f);
        size_t base = (size_t)n * 3600 + (size_t)(tile * 5 + wp) * 30 + l;
        g_buf1[base]        = m[0];
        g_buf1[base + 900]  = m[1];
        g_buf1[base + 1800] = m[2];
        g_buf1[base + 2700] = m[3];
    }

    // BN1 stats: warp shfl-reduce (doubles) -> smem atomics -> 8 global adds
#pragma unroll
    for (int oc = 0; oc < 4; ++oc) {
        double sv = (double)m[oc];
        double sq = sv * sv;
#pragma unroll
        for (int off = 16; off > 0; off >>= 1) {
            sv += __shfl_down_sync(0xffffffffu, sv, off);
            sq += __shfl_down_sync(0xffffffffu, sq, off);
        }
        if (l == 0) {
            atomicAdd(&s_st[oc], sv);
            atomicAdd(&s_st[4 + oc], sq);
        }
    }
    __syncthreads();
    if (tid < 8) atomicAdd(&g_bn1[tid], s_st[tid]);
}

// ---------------- conv2: BN1 affine + 4->8ch 9x9 s2, relu+bias, pool2, BN2 -
__global__ __launch_bounds__(256) void k_conv2(const float* __restrict__ w,
                                               const float* __restrict__ bias,
                                               const float* __restrict__ bn1g,
                                               const float* __restrict__ bn1b) {
    __shared__ __align__(16) float img[3600];     // [ic][30][30], BN applied
    __shared__ __align__(16) float ws[2592];      // [tap][oc]
    __shared__ float out2[968];                   // [oc][11][11]
    __shared__ float sc[4], shf[4], sb[8];
    __shared__ double st[16];

    const int tid = threadIdx.x;
    const int n = blockIdx.x;

    if (tid < 4) {
        double mu = g_bn1[tid] / 720000.0;
        double var = g_bn1[4 + tid] / 720000.0 - mu * mu;
        float s = bn1g[tid] * rsqrtf((float)var + 1e-5f);
        sc[tid] = s;
        shf[tid] = bn1b[tid] - (float)mu * s;
    }
    if (tid < 8)  sb[tid] = bias[tid];
    if (tid < 16) st[tid] = 0.0;
    for (int j = tid; j < 2592; j += 256) {
        int oc = j & 7, tap = j >> 3;
        ws[j] = w[oc * 324 + tap];
    }
    __syncthreads();

    {   // vectorized BN-applied staging: 900 float4, c = j/225
        const float4* src = (const float4*)(g_buf1 + (size_t)n * 3600);
        for (int j = tid; j < 900; j += 256) {
            float4 v = src[j];
            int c = j / 225;
            float s = sc[c], h = shf[c];
            v.x = s * v.x + h; v.y = s * v.y + h;
            v.z = s * v.z + h; v.w = s * v.w + h;
            ((float4*)img)[j] = v;
        }
    }
    __syncthreads();

    if (tid < 242) {
        const int p = tid >> 1, half = tid & 1;   // 121 positions x 2 halves of 4 oc
        const int orow = p / 11, ocol = p % 11;
        unsigned long long a2c[2] = {0ull, 0ull};
        for (int ic = 0; ic < 4; ++ic) {
            const float* base = img + ic * 900 + (2 * orow) * 30 + 2 * ocol;
            const float* wb = ws + (ic * 81) * 8 + half * 4;
#pragma unroll
            for (int ky = 0; ky < 9; ++ky)
#pragma unroll
                for (int kx = 0; kx < 9; ++kx) {
                    unsigned long long d = pk2(base[ky * 30 + kx]);
                    ulonglong2 wv = *(const ulonglong2*)(wb + (ky * 9 + kx) * 8);
                    ffma2(a2c[0], d, wv.x);
                    ffma2(a2c[1], d, wv.y);
                }
        }
        float2 r0 = upk2(a2c[0]), r1 = upk2(a2c[1]);
        float accv[4] = {r0.x, r0.y, r1.x, r1.y};
#pragma unroll
        for (int qq = 0; qq < 4; ++qq) {
            int oc = half * 4 + qq;
            out2[oc * 121 + p] = fmaxf(accv[qq] + sb[oc], 0.f);
        }
    }
    __syncthreads();

    if (tid < 200) {
        int oc = tid / 25, r = tid % 25;
        int pr = r / 5, pc = r % 5;
        const float* o = out2 + oc * 121 + (2 * pr) * 11 + 2 * pc;
        float v = fmaxf(fmaxf(o[0], o[1]), fmaxf(o[11], o[12]));
        g_buf2[(size_t)n * 200 + tid] = v;
        atomicAdd(&st[oc], (double)v);
        atomicAdd(&st[8 + oc], (double)v * (double)v);
    }
    __syncthreads();
    if (tid < 16) atomicAdd(&g_bn2[tid], st[tid]);
}

// ---------------- FC stack: warp-per-sample, 200 blocks x 4 warps ----------
__global__ __launch_bounds__(128) void k_fc(const float* __restrict__ bn2g,
                                            const float* __restrict__ bn2b,
                                            const float* __restrict__ w1,
                                            const float* __restrict__ b1,
                                            const float* __restrict__ w2,
                                            const float* __restrict__ b2,
                                            const float* __restrict__ wz,
                                            const float* __restrict__ bz,
                                            const float* __restrict__ wL,
                                            const float* __restrict__ bL) {
    __shared__ __align__(16) float s_w1[16 * 204];  // padded stride 204
    __shared__ float s_w2t[512];                    // transposed: [k][o]
    __shared__ float s_wz[64], s_wL[96];
    __shared__ float s_b1[16], s_b2[32], s_bz[2], s_bL[3];
    __shared__ float sc[8], shf[8];
    __shared__ __align__(16) float sf[4][200];      // per-warp BN-applied features
    const int tid = threadIdx.x;
    const int wp = tid >> 5, l = tid & 31;
    const int s = blockIdx.x * 4 + wp;              // < 800 always

    // prefetch raw features FIRST (overlap gmem latency with weight staging)
    float raw[7];
    {
        const float* f = g_buf2 + (size_t)s * 200;
#pragma unroll
        for (int j = 0; j < 7; ++j) {
            int i = l + 32 * j;
            raw[j] = (i < 200) ? f[i] : 0.f;
        }
    }

    if (tid < 8) {
        double mu = g_bn2[tid] / 20000.0;
        double var = g_bn2[8 + tid] / 20000.0 - mu * mu;
        float ss = bn2g[tid] * rsqrtf((float)var + 1e-5f);
        sc[tid] = ss;
        shf[tid] = bn2b[tid] - (float)mu * ss;
    }
    for (int j = tid; j < 800; j += 128) {
        float4 v = ((const float4*)w1)[j];
        int o = j / 50, k0 = (j % 50) * 4;
        *(float4*)(s_w1 + o * 204 + k0) = v;
    }
    for (int i = tid; i < 512; i += 128) {
        int k = i >> 5, o = i & 31;
        s_w2t[i] = w2[o * 16 + k];
    }
    if (tid < 64) s_wz[tid] = wz[tid];
    if (tid < 96) s_wL[tid] = wL[tid];
    if (tid < 16) s_b1[tid] = b1[tid];
    if (tid < 32) s_b2[tid] = b2[tid];
    if (tid < 2)  s_bz[tid] = bz[tid];
    if (tid < 3)  s_bL[tid] = bL[tid];
    __syncthreads();

#pragma unroll
    for (int j = 0; j < 7; ++j) {
        int i = l + 32 * j;
        if (i < 200) {
            int c = i / 25;
            sf[wp][i] = sc[c] * raw[j] + shf[c];
        }
    }
    __syncwarp();

    // fc1: o = l&15, half h = l>>4 covers k in [100h, 100h+100); 4-acc float4
    const int o16 = l & 15, h = l >> 4;
    float a;
    {
        const float4* wr = (const float4*)(s_w1 + o16 * 204 + h * 100);
        const float4* fr = (const float4*)(sf[wp] + h * 100);
        float a0 = 0.f, a1_ = 0.f, a2_ = 0.f, a3 = 0.f;
#pragma unroll
        for (int k = 0; k < 25; ++k) {
            float4 wv = wr[k], fv = fr[k];
            a0 += fv.x * wv.x;
            a1_ += fv.y * wv.y;
            a2_ += fv.z * wv.z;
            a3 += fv.w * wv.w;
        }
        a = (a0 + a1_) + (a2_ + a3);
        if (h == 0) a += s_b1[o16];
    }
    a += __shfl_xor_sync(0xffffffffu, a, 16);
    float a1 = fmaxf(a, 0.f);

    // fc2: lane l -> neuron l
    float t2 = s_b2[l];
#pragma unroll
    for (int k = 0; k < 16; ++k) {
        float ak = __shfl_sync(0xffffffffu, a1, k);
        t2 += ak * s_w2t[k * 32 + l];
    }
    float a2 = fmaxf(t2, 0.f);

    // fc3: 5 dot-products over 32 lanes
    float p0 = a2 * s_wz[l];
    float p1 = a2 * s_wz[32 + l];
    float q0 = a2 * s_wL[l];
    float q1 = a2 * s_wL[32 + l];
    float q2 = a2 * s_wL[64 + l];
#pragma unroll
    for (int off = 16; off > 0; off >>= 1) {
        p0 += __shfl_down_sync(0xffffffffu, p0, off);
        p1 += __shfl_down_sync(0xffffffffu, p1, off);
        q0 += __shfl_down_sync(0xffffffffu, q0, off);
        q1 += __shfl_down_sync(0xffffffffu, q1, off);
        q2 += __shfl_down_sync(0xffffffffu, q2, off);
    }
    if (l == 0) {
        float z0 = p0 + s_bz[0], z1 = p1 + s_bz[1];
        float L0 = q0 + s_bL[0], L1 = q1 + s_bL[1], L2 = q2 + s_bL[2];
        float* o = g_zR + (size_t)s * 6;
        o[0] = z0; o[1] = z1;
        o[2] = L0 * L0; o[3] = L0 * L1; o[4] = L0 * L1; o[5] = L1 * L1 + L2 * L2;
    }
}

// ---------------- Kalman filter: ONE warp, 8 sequences x 4 lanes, all-shfl --
__global__ __launch_bounds__(32) void k_kf(float* __restrict__ out,
                                           const float* __restrict__ A,
                                           const float* __restrict__ B,
                                           const float* __restrict__ C,
                                           const float* __restrict__ Q) {
    __shared__ float zsm[4800];
    const int l = threadIdx.x;
    for (int i = l; i < 4800; i += 32) zsm[i] = g_zR[i];
    __syncwarp();

    const int g = l >> 2, j = l & 3;
    const int base = l & 28;
    const unsigned FULL = 0xffffffffu;

    float a_[16], c_[8];
#pragma unroll
    for (int i = 0; i < 16; ++i) a_[i] = A[i];
#pragma unroll
    for (int i = 0; i < 8; ++i) c_[i] = C[i];
    float bq[4];
    {
        float BQ[8];
#pragma unroll
        for (int i = 0; i < 4; ++i)
#pragma unroll
            for (int k = 0; k < 2; ++k) {
                float t = 0.f;
#pragma unroll
                for (int q2 = 0; q2 < 2; ++q2) t += B[i * 2 + q2] * Q[q2 * 2 + k];
                BQ[i * 2 + k] = t;
            }
#pragma unroll
        for (int i = 0; i < 4; ++i) {
            float t = 0.f;
#pragma unroll
            for (int k = 0; k < 2; ++k) t += BQ[i * 2 + k] * B[j * 2 + k];
            bq[i] = t;
        }
    }

    const float* zb = zsm + g * 600;

    float hj = (j < 2) ? zb[j] : 0.f;
    float sc_[4];
    if (j < 2) { sc_[0] = zb[2 + j]; sc_[1] = zb[4 + j]; sc_[2] = 0.f; sc_[3] = 0.f; }
    else       { sc_[0] = 0.f; sc_[1] = 0.f; sc_[2] = (j == 2) ? 1.f : 0.f; sc_[3] = (j == 3) ? 1.f : 0.f; }
    out[g * 400 + j] = hj;

    for (int t = 1; t < 100; ++t) {
        const float* zr = zb + t * 6;
        float z0 = zr[0], z1 = zr[1];
        float R00 = zr[2], R01 = zr[3], R10 = zr[4], R11 = zr[5];

        float h0 = __shfl_sync(FULL, hj, base);
        float h1 = __shfl_sync(FULL, hj, base + 1);
        float h2 = __shfl_sync(FULL, hj, base + 2);
        float h3 = __shfl_sync(FULL, hj, base + 3);
        float hp = a_[j * 4] * h0 + a_[j * 4 + 1] * h1 + a_[j * 4 + 2] * h2 + a_[j * 4 + 3] * h3;

        float t1[4];
#pragma unroll
        for (int i = 0; i < 4; ++i)
            t1[i] = a_[i * 4] * sc_[0] + a_[i * 4 + 1] * sc_[1] + a_[i * 4 + 2] * sc_[2] + a_[i * 4 + 3] * sc_[3];

        float sp[4] = {bq[0], bq[1], bq[2], bq[3]};
#pragma unroll
        for (int k = 0; k < 4; ++k) {
            float ajk = a_[j * 4 + k];
            float u0 = __shfl_sync(FULL, t1[0], base + k);
            float u1 = __shfl_sync(FULL, t1[1], base + k);
            float u2 = __shfl_sync(FULL, t1[2], base + k);
            float u3 = __shfl_sync(FULL, t1[3], base + k);
            sp[0] += u0 * ajk; sp[1] += u1 * ajk; sp[2] += u2 * ajk; sp[3] += u3 * ajk;
        }

        float hp0 = __shfl_sync(FULL, hp, base);
        float hp1 = __shfl_sync(FULL, hp, base + 1);
        float hp2 = __shfl_sync(FULL, hp, base + 2);
        float hp3 = __shfl_sync(FULL, hp, base + 3);
        float al0 = z0 - (c_[0] * hp0 + c_[1] * hp1 + c_[2] * hp2 + c_[3] * hp3);
        float al1 = z1 - (c_[4] * hp0 + c_[5] * hp1 + c_[6] * hp2 + c_[7] * hp3);

        float w0[4], w1[4];
        float c0j = c_[j], c1j = c_[4 + j];
#pragma unroll
        for (int i = 0; i < 4; ++i) { w0[i] = sp[i] * c0j; w1[i] = sp[i] * c1j; }
#pragma unroll
        for (int off = 1; off <= 2; off <<= 1) {
#pragma unroll
            for (int i = 0; i < 4; ++i) {
                w0[i] += __shfl_xor_sync(FULL, w0[i], off);
                w1[i] += __shfl_xor_sync(FULL, w1[i], off);
            }
        }

        float S00 = c_[0] * w0[0] + c_[1] * w0[1] + c_[2] * w0[2] + c_[3] * w0[3] + R00;
        float S01 = c_[0] * w1[0] + c_[1] * w1[1] + c_[2] * w1[2] + c_[3] * w1[3] + R01;
        float S10 = c_[4] * w0[0] + c_[5] * w0[1] + c_[6] * w0[2] + c_[7] * w0[3] + R10;
        float S11 = c_[4] * w1[0] + c_[5] * w1[1] + c_[6] * w1[2] + c_[7] * w1[3] + R11;
        float inv = 1.0f / (S00 * S11 - S01 * S10);
        float Si00 = S11 * inv, Si01 = -S01 * inv, Si10 = -S10 * inv, Si11 = S00 * inv;

        float K0[4], K1[4];
#pragma unroll
        for (int i = 0; i < 4; ++i) {
            K0[i] = w0[i] * Si00 + w1[i] * Si10;
            K1[i] = w0[i] * Si01 + w1[i] * Si11;
        }

        hj = hp + K0[j] * al0 + K1[j] * al1;
        out[(g * 100 + t) * 4 + j] = hj;

        float cs0 = c_[0] * sp[0] + c_[1] * sp[1] + c_[2] * sp[2] + c_[3] * sp[3];
        float cs1 = c_[4] * sp[0] + c_[5] * sp[1] + c_[6] * sp[2] + c_[7] * sp[3];
#pragma unroll
        for (int i = 0; i < 4; ++i) sc_[i] = sp[i] - K0[i] * cs0 - K1[i] * cs1;
    }
}

// ---------------- launch ---------------------------------------------------
// Order: conv1, conv2, fc, kf, zero  (zero re-arms stats for the next replay;
// device globals are zero-initialized for the very first run).
// Side effect: launch index 5 in the replay stream is k_conv1 -> ncu -s 5
// captures the dominant kernel next round.
extern "C" void kernel_launch(void* const* d_in, const int* in_sizes, int n_in,
                              void* d_out, int out_size) {
    const float* x    = (const float*)d_in[0];
    const float* c1w  = (const float*)d_in[1];
    const float* c1b  = (const float*)d_in[2];
    const float* bn1g = (const float*)d_in[3];
    const float* bn1b = (const float*)d_in[4];
    const float* c2w  = (const float*)d_in[5];
    const float* c2b  = (const float*)d_in[6];
    const float* bn2g = (const float*)d_in[7];
    const float* bn2b = (const float*)d_in[8];
    const float* f1w  = (const float*)d_in[9];
    const float* f1b  = (const float*)d_in[10];
    const float* f2w  = (const float*)d_in[11];
    const float* f2b  = (const float*)d_in[12];
    const float* fzw  = (const float*)d_in[13];
    const float* fzb  = (const float*)d_in[14];
    const float* fLw  = (const float*)d_in[15];
    const float* fLb  = (const float*)d_in[16];
    const float* A    = (const float*)d_in[17];
    const float* B    = (const float*)d_in[18];
    const float* C    = (const float*)d_in[19];
    const float* Q    = (const float*)d_in[20];
    float* out = (float*)d_out;

    k_conv1<<<4800, 160>>>(x, c1w, c1b);
    k_conv2<<<800, 256>>>(c2w, c2b, bn1g, bn1b);
    k_fc<<<200, 128>>>(bn2g, bn2b, f1w, f1b, f2w, f2b, fzw, fzb, fLw, fLb);
    k_kf<<<1, 32>>>(out, A, B, C, Q);
    k_zero<<<1, 32>>>();
}